// round 9
// baseline (speedup 1.0000x reference)
#include <cuda_runtime.h>
#include <cuda_bf16.h>
#include <math.h>
#include <stdint.h>

#define B_ 2
#define T_ 2048
#define D_ 1024
#define H_ 16
#define DH_ 64
#define SCALE_ 0.03125f     /* 1/sqrt(1024) exactly */

#define ASTRIDE ((size_t)4096*1024)
#define WSTRIDE ((size_t)1024*1024)

// ============================================================================
// Scratch (static device globals — no allocation in kernel_launch)
// ============================================================================
__device__ float g_CTX[(size_t)B_*T_*D_];
__device__ __nv_bfloat16 g_Ah[3*ASTRIDE];
__device__ __nv_bfloat16 g_Al[3*ASTRIDE];
__device__ __nv_bfloat16 g_Wh[4*WSTRIDE];
__device__ __nv_bfloat16 g_Wl[4*WSTRIDE];
__device__ __nv_bfloat16 g_Qh[(size_t)B_*H_*T_*DH_];
__device__ __nv_bfloat16 g_Ql[(size_t)B_*H_*T_*DH_];
__device__ __nv_bfloat16 g_Kh[(size_t)B_*H_*T_*DH_];   // compacted
__device__ __nv_bfloat16 g_Kl[(size_t)B_*H_*T_*DH_];   // compacted
__device__ __nv_bfloat16 g_Vh[(size_t)B_*H_*T_*DH_];   // compacted
__device__ __nv_bfloat16 g_Vl[(size_t)B_*H_*T_*DH_];   // compacted
__device__ int g_pos[B_*T_];
__device__ int g_cnt[B_];

// ============================================================================
// mma.sync / ldmatrix / cp.async helpers (base-target PTX)
// ============================================================================
__device__ __forceinline__ unsigned smem_u32(const void* p) {
    unsigned a;
    asm("{ .reg .u64 t; cvta.to.shared.u64 t, %1; cvt.u32.u64 %0, t; }"
        : "=r"(a) : "l"(p));
    return a;
}
__device__ __forceinline__ void mma_bf(float* c, const unsigned* a, const unsigned* b) {
    asm volatile(
        "mma.sync.aligned.m16n8k16.row.col.f32.bf16.bf16.f32 "
        "{%0,%1,%2,%3}, {%4,%5,%6,%7}, {%8,%9}, {%0,%1,%2,%3};"
        : "+f"(c[0]), "+f"(c[1]), "+f"(c[2]), "+f"(c[3])
        : "r"(a[0]), "r"(a[1]), "r"(a[2]), "r"(a[3]), "r"(b[0]), "r"(b[1]));
}
__device__ __forceinline__ void ldsm4(unsigned* r, unsigned a) {
    asm volatile("ldmatrix.sync.aligned.m8n8.x4.shared.b16 {%0,%1,%2,%3}, [%4];"
        : "=r"(r[0]), "=r"(r[1]), "=r"(r[2]), "=r"(r[3]) : "r"(a));
}
__device__ __forceinline__ void ldsm4t(unsigned* r, unsigned a) {
    asm volatile("ldmatrix.sync.aligned.m8n8.x4.trans.shared.b16 {%0,%1,%2,%3}, [%4];"
        : "=r"(r[0]), "=r"(r[1]), "=r"(r[2]), "=r"(r[3]) : "r"(a));
}
#define CP16(dst_u32, src_ptr) \
    asm volatile("cp.async.cg.shared.global [%0], [%1], 16;" \
        :: "r"(dst_u32), "l"(src_ptr) : "memory")
#define CP_COMMIT() asm volatile("cp.async.commit_group;" ::: "memory")
#define CP_WAIT1()  asm volatile("cp.async.wait_group 1;"  ::: "memory")

// ============================================================================
// scan_mask
// ============================================================================
__global__ void __launch_bounds__(1024) scan_mask(const int* __restrict__ mask)
{
    __shared__ int ps[1024];
    const int b = blockIdx.x, i = threadIdx.x;
    const int a0 = (mask[b*T_ + 2*i]     != 0);
    const int a1 = (mask[b*T_ + 2*i + 1] != 0);
    ps[i] = a0 + a1;
    __syncthreads();
    for (int off = 1; off < 1024; off <<= 1) {
        int v = ps[i] + ((i >= off) ? ps[i - off] : 0);
        __syncthreads();
        ps[i] = v;
        __syncthreads();
    }
    const int excl = (i > 0) ? ps[i-1] : 0;
    g_pos[b*T_ + 2*i]     = a0 ? excl : -1;
    g_pos[b*T_ + 2*i + 1] = a1 ? (excl + a0) : -1;
    if (i == 1023) g_cnt[b] = ps[1023];
}

// ============================================================================
// conv_split core + batched wrappers
// ============================================================================
__device__ __forceinline__ void conv_one(
    const float* __restrict__ x, __nv_bfloat16* __restrict__ hi,
    __nv_bfloat16* __restrict__ lo, int i)
{
    float4 v = ((const float4*)x)[i];
    __nv_bfloat16 h0 = __float2bfloat16_rn(v.x);
    __nv_bfloat16 h1 = __float2bfloat16_rn(v.y);
    __nv_bfloat16 h2 = __float2bfloat16_rn(v.z);
    __nv_bfloat16 h3 = __float2bfloat16_rn(v.w);
    __nv_bfloat162 ha; ha.x = h0; ha.y = h1;
    __nv_bfloat162 hb; hb.x = h2; hb.y = h3;
    __nv_bfloat162 la, lb;
    la.x = __float2bfloat16_rn(v.x - __bfloat162float(h0));
    la.y = __float2bfloat16_rn(v.y - __bfloat162float(h1));
    lb.x = __float2bfloat16_rn(v.z - __bfloat162float(h2));
    lb.y = __float2bfloat16_rn(v.w - __bfloat162float(h3));
    ((__nv_bfloat162*)hi)[2*i]   = ha;
    ((__nv_bfloat162*)hi)[2*i+1] = hb;
    ((__nv_bfloat162*)lo)[2*i]   = la;
    ((__nv_bfloat162*)lo)[2*i+1] = lb;
}

__global__ void __launch_bounds__(256) convA3(
    const float* __restrict__ q, const float* __restrict__ k,
    const float* __restrict__ v,
    __nv_bfloat16* __restrict__ hiB, __nv_bfloat16* __restrict__ loB)
{
    const int z = blockIdx.y;
    const float* src = (z == 0) ? q : (z == 1) ? k : v;
    int i = blockIdx.x * 256 + threadIdx.x;
    conv_one(src, hiB + z*ASTRIDE, loB + z*ASTRIDE, i);
}

__global__ void __launch_bounds__(256) convA1(
    const float* __restrict__ x,
    __nv_bfloat16* __restrict__ hiB, __nv_bfloat16* __restrict__ loB)
{
    int i = blockIdx.x * 256 + threadIdx.x;
    conv_one(x, hiB, loB, i);
}

__global__ void __launch_bounds__(256) convW4(
    const float* __restrict__ wq, const float* __restrict__ wk,
    const float* __restrict__ wv, const float* __restrict__ wo,
    __nv_bfloat16* __restrict__ hiB, __nv_bfloat16* __restrict__ loB)
{
    const int z = blockIdx.y;
    const float* src = (z == 0) ? wq : (z == 1) ? wk : (z == 2) ? wv : wo;
    int i = blockIdx.x * 256 + threadIdx.x;
    conv_one(src, hiB + z*WSTRIDE, loB + z*WSTRIDE, i);
}

// ============================================================================
// GEMM core (split-bf16 3-stream, cp.async 3-stage pipeline, 1 sync/iter)
// ============================================================================
#define GST 37888
#define G_AL_OFF 10240
#define G_WH_OFF 20480
#define G_WL_OFF 29184
#define GEMM_SMEM (3*GST)

__device__ __forceinline__ void gemm_core(
    char* gsm,
    const __nv_bfloat16* __restrict__ Ah, const __nv_bfloat16* __restrict__ Al,
    const __nv_bfloat16* __restrict__ Wh, const __nv_bfloat16* __restrict__ Wl,
    const float* __restrict__ bias,
    float* __restrict__ Yf,
    __nv_bfloat16* __restrict__ Yh, __nv_bfloat16* __restrict__ Yl,
    int mode, int m0, int n0)
{
    const int tid = threadIdx.x, lane = tid & 31, wid = tid >> 5;
    const int wm = wid >> 2, wn = wid & 3;

    float c[4][4][4];
    #pragma unroll
    for (int i = 0; i < 4; i++)
        #pragma unroll
        for (int j = 0; j < 4; j++)
            #pragma unroll
            for (int e = 0; e < 4; e++) c[i][j][e] = 0.f;

    const int l15 = lane & 15, lh8 = (lane >> 4) << 3;
    const unsigned smb = smem_u32(gsm);

    int a_row[2], a_c8[2], w_row[2], w_c8[2];
    #pragma unroll
    for (int t = 0; t < 2; t++) {
        int ch = tid + t*256;
        a_row[t] = ch >> 2;  a_c8[t] = (ch & 3) << 3;
        w_row[t] = ch >> 4;  w_c8[t] = (ch & 15) << 3;
    }

    auto issue = [&](int s, int k0) {
        const unsigned base = smb + s*GST;
        #pragma unroll
        for (int t = 0; t < 2; t++) {
            unsigned aso = base + (unsigned)(a_row[t]*80 + a_c8[t]*2);
            size_t ago = (size_t)(m0 + a_row[t])*1024 + k0 + a_c8[t];
            CP16(aso,            Ah + ago);
            CP16(aso + G_AL_OFF, Al + ago);
            unsigned wso = base + G_WH_OFF + (unsigned)(w_row[t]*272 + w_c8[t]*2);
            size_t wgo = (size_t)(k0 + w_row[t])*1024 + n0 + w_c8[t];
            CP16(wso,                       Wh + wgo);
            CP16(wso + (G_WL_OFF-G_WH_OFF), Wl + wgo);
        }
    };

    // Prologue: chunks 0 and 1 into stages 0 and 1
    issue(0, 0);
    CP_COMMIT();
    issue(1, 32);
    CP_COMMIT();

    for (int kc = 0; kc < 32; kc++) {
        // chunk kc resident (one newer group may still be in flight)
        CP_WAIT1();
        __syncthreads();
        // stage (kc+2)%3 was last read in iteration kc-1; sync above makes
        // the overwrite safe. Always commit: keeps group<->chunk accounting
        // uniform so wait_group 1 is exact through the tail.
        if (kc + 2 < 32) issue((kc + 2) % 3, (kc + 2) << 5);
        CP_COMMIT();

        const int buf = kc % 3;
        const __nv_bfloat16* sAh = (const __nv_bfloat16*)(gsm + buf*GST);
        const __nv_bfloat16* sAl = (const __nv_bfloat16*)(gsm + buf*GST + G_AL_OFF);
        const __nv_bfloat16* sWh = (const __nv_bfloat16*)(gsm + buf*GST + G_WH_OFF);
        const __nv_bfloat16* sWl = (const __nv_bfloat16*)(gsm + buf*GST + G_WL_OFF);

        #pragma unroll
        for (int kk = 0; kk < 32; kk += 16) {
            unsigned a[4][4], bh_[4][2], bl_[4][2], t4[4];
            #pragma unroll
            for (int mi = 0; mi < 4; mi++)
                ldsm4(a[mi], smem_u32(&sAh[(wm*64 + mi*16 + l15)*40 + kk + lh8]));
            #pragma unroll
            for (int p = 0; p < 2; p++) {
                ldsm4t(t4, smem_u32(&sWh[(kk + l15)*136 + wn*32 + p*16 + lh8]));
                bh_[2*p][0]=t4[0]; bh_[2*p][1]=t4[1];
                bh_[2*p+1][0]=t4[2]; bh_[2*p+1][1]=t4[3];
                ldsm4t(t4, smem_u32(&sWl[(kk + l15)*136 + wn*32 + p*16 + lh8]));
                bl_[2*p][0]=t4[0]; bl_[2*p][1]=t4[1];
                bl_[2*p+1][0]=t4[2]; bl_[2*p+1][1]=t4[3];
            }
            #pragma unroll
            for (int mi = 0; mi < 4; mi++)
                #pragma unroll
                for (int ni = 0; ni < 4; ni++) mma_bf(c[mi][ni], a[mi], bh_[ni]);
            #pragma unroll
            for (int mi = 0; mi < 4; mi++)
                #pragma unroll
                for (int ni = 0; ni < 4; ni++) mma_bf(c[mi][ni], a[mi], bl_[ni]);
            #pragma unroll
            for (int mi = 0; mi < 4; mi++)
                ldsm4(a[mi], smem_u32(&sAl[(wm*64 + mi*16 + l15)*40 + kk + lh8]));
            #pragma unroll
            for (int mi = 0; mi < 4; mi++)
                #pragma unroll
                for (int ni = 0; ni < 4; ni++) mma_bf(c[mi][ni], a[mi], bh_[ni]);
        }
    }

    // Epilogue
    const int rA = lane >> 2, c2 = (lane & 3) << 1;
    #pragma unroll
    for (int mi = 0; mi < 4; mi++) {
        const int rowA = m0 + wm*64 + mi*16 + rA;
        const int rowB = rowA + 8;
        int pA = rowA & (T_-1), pB = rowB & (T_-1);
        if (mode == 1) { pA = g_pos[rowA]; pB = g_pos[rowB]; }
        #pragma unroll
        for (int ni = 0; ni < 4; ni++) {
            const int col = n0 + wn*32 + ni*8 + c2;
            float2 bb = *(const float2*)(bias + col);
            float v00 = c[mi][ni][0] + bb.x, v01 = c[mi][ni][1] + bb.y;
            float v10 = c[mi][ni][2] + bb.x, v11 = c[mi][ni][3] + bb.y;
            if (mode == 2) {
                float2 w0; w0.x = v00; w0.y = v01;
                float2 w1; w1.x = v10; w1.y = v11;
                *(float2*)(Yf + (size_t)rowA * 1024 + col) = w0;
                *(float2*)(Yf + (size_t)rowB * 1024 + col) = w1;
            } else {
                const int hh = col >> 6, dd = col & 63;
                const int bA = rowA >> 11, bB = rowB >> 11;
                __nv_bfloat16 h00 = __float2bfloat16_rn(v00);
                __nv_bfloat16 h01 = __float2bfloat16_rn(v01);
                __nv_bfloat16 h10 = __float2bfloat16_rn(v10);
                __nv_bfloat16 h11 = __float2bfloat16_rn(v11);
                __nv_bfloat162 ph0; ph0.x=h00; ph0.y=h01;
                __nv_bfloat162 ph1; ph1.x=h10; ph1.y=h11;
                __nv_bfloat162 pl0, pl1;
                pl0.x = __float2bfloat16_rn(v00 - __bfloat162float(h00));
                pl0.y = __float2bfloat16_rn(v01 - __bfloat162float(h01));
                pl1.x = __float2bfloat16_rn(v10 - __bfloat162float(h10));
                pl1.y = __float2bfloat16_rn(v11 - __bfloat162float(h11));
                if (pA >= 0) {
                    size_t oA = (((size_t)(bA*H_ + hh))*T_ + pA)*64 + dd;
                    *(__nv_bfloat162*)(Yh + oA) = ph0;
                    *(__nv_bfloat162*)(Yl + oA) = pl0;
                }
                if (pB >= 0) {
                    size_t oB = (((size_t)(bB*H_ + hh))*T_ + pB)*64 + dd;
                    *(__nv_bfloat162*)(Yh + oB) = ph1;
                    *(__nv_bfloat162*)(Yl + oB) = pl1;
                }
            }
        }
    }
}

// Batched QKV projection: blockIdx.z selects {Q,K,V}
__global__ void __launch_bounds__(256, 2) gemm_qkv(
    const __nv_bfloat16* __restrict__ AhB, const __nv_bfloat16* __restrict__ AlB,
    const __nv_bfloat16* __restrict__ WhB, const __nv_bfloat16* __restrict__ WlB,
    const float* __restrict__ bq, const float* __restrict__ bk,
    const float* __restrict__ bv,
    __nv_bfloat16* __restrict__ Qh, __nv_bfloat16* __restrict__ Ql,
    __nv_bfloat16* __restrict__ Kh, __nv_bfloat16* __restrict__ Kl,
    __nv_bfloat16* __restrict__ Vh, __nv_bfloat16* __restrict__ Vl)
{
    extern __shared__ __align__(16) char gsm[];
    const int z = blockIdx.z;
    const float* bias = (z == 0) ? bq : (z == 1) ? bk : bv;
    __nv_bfloat16* Yh = (z == 0) ? Qh : (z == 1) ? Kh : Vh;
    __nv_bfloat16* Yl = (z == 0) ? Ql : (z == 1) ? Kl : Vl;
    gemm_core(gsm, AhB + z*ASTRIDE, AlB + z*ASTRIDE,
              WhB + z*WSTRIDE, WlB + z*WSTRIDE, bias,
              nullptr, Yh, Yl, (z == 0) ? 0 : 1,
              blockIdx.y << 7, blockIdx.x << 7);
}

// Output projection (dense fp32)
__global__ void __launch_bounds__(256, 2) gemm_out(
    const __nv_bfloat16* __restrict__ AhB, const __nv_bfloat16* __restrict__ AlB,
    const __nv_bfloat16* __restrict__ WhB, const __nv_bfloat16* __restrict__ WlB,
    const float* __restrict__ bo, float* __restrict__ out)
{
    extern __shared__ __align__(16) char gsm[];
    gemm_core(gsm, AhB, AlB, WhB + 3*WSTRIDE, WlB + 3*WSTRIDE, bo,
              out, nullptr, nullptr, 2, blockIdx.y << 7, blockIdx.x << 7);
}

// ============================================================================
// Flash attention (unchanged from R7 passing version)
// ============================================================================
#define ATT_QH   0
#define ATT_QL   18432
#define ATT_K    36864
#define ATT_V    73728
#define ATT_PH   110592
#define ATT_PL   129024
#define ATT_PSUM 147456
#define ATT_LS   149504
#define ATT_SMEM 150016

__global__ void __launch_bounds__(256) attn_mma()
{
    extern __shared__ __align__(16) char sm[];
    __nv_bfloat16* sQh = (__nv_bfloat16*)(sm + ATT_QH);
    __nv_bfloat16* sQl = (__nv_bfloat16*)(sm + ATT_QL);
    __nv_bfloat16* sPh = (__nv_bfloat16*)(sm + ATT_PH);
    __nv_bfloat16* sPl = (__nv_bfloat16*)(sm + ATT_PL);
    float* psum = (float*)(sm + ATT_PSUM);
    float* l_s  = (float*)(sm + ATT_LS);

    const int tid = threadIdx.x, lane = tid & 31, wid = tid >> 5;
    const int wm = wid >> 2, wn = wid & 3;
    const int qt0 = blockIdx.x << 7;
    const int hh = blockIdx.y, bb = blockIdx.z;
    const size_t base = ((size_t)(bb*H_ + hh)) * T_ * DH_;
    const int nv = g_cnt[bb];
    const int nt = (nv + 63) >> 6;

    const int r = tid >> 1, cofs = (tid & 1) << 5;
    const int l15 = lane & 15, lh8 = (lane >> 4) << 3;
    const int bn  = (lane & 7) + ((lane >> 4) << 3), bk8 = ((lane >> 3) & 1) << 3;
    const int rA0 = lane >> 2, c2 = (lane & 3) << 1;

    const unsigned smK = smem_u32(sm + ATT_K);
    const unsigned smV = smem_u32(sm + ATT_V);

    int ld_row[2], ld_c8[2];
    #pragma unroll
    for (int t = 0; t < 2; t++) {
        int ch = tid + t*256;
        ld_row[t] = ch >> 3;
        ld_c8[t]  = (ch & 7) << 3;
    }

    {
        const uint4* s1 = (const uint4*)(g_Qh + base + (size_t)(qt0 + r)*64 + cofs);
        uint4* d1 = (uint4*)(sQh + r*72 + cofs);
        d1[0]=s1[0]; d1[1]=s1[1]; d1[2]=s1[2]; d1[3]=s1[3];
        const uint4* s2 = (const uint4*)(g_Ql + base + (size_t)(qt0 + r)*64 + cofs);
        uint4* d2 = (uint4*)(sQl + r*72 + cofs);
        d2[0]=s2[0]; d2[1]=s2[1]; d2[2]=s2[2]; d2[3]=s2[3];
    }
    if (tid < 128) l_s[tid] = 0.f;

    float o[4][2][4];
    #pragma unroll
    for (int i = 0; i < 4; i++)
        #pragma unroll
        for (int j = 0; j < 2; j++)
            #pragma unroll
            for (int e = 0; e < 4; e++) o[i][j][e] = 0.f;

    #pragma unroll
    for (int t = 0; t < 2; t++) {
        unsigned so = (unsigned)((ld_row[t]*72 + ld_c8[t]) * 2);
        size_t go = base + (size_t)ld_row[t]*64 + ld_c8[t];
        CP16(smK + so,         g_Kh + go);
        CP16(smK + 9216u + so, g_Kl + go);
        CP16(smV + so,         g_Vh + go);
        CP16(smV + 9216u + so, g_Vl + go);
    }
    CP_COMMIT();

    for (int kt = 0; kt < nt; kt++) {
        const int buf = kt & 1;
        if (kt + 1 < nt) {
            const size_t gofs = base + ((size_t)(kt+1) << 6) * 64;
            const unsigned kb = smK + (buf ^ 1) * 18432u;
            const unsigned vb = smV + (buf ^ 1) * 18432u;
            #pragma unroll
            for (int t = 0; t < 2; t++) {
                unsigned so = (unsigned)((ld_row[t]*72 + ld_c8[t]) * 2);
                size_t go = gofs + (size_t)ld_row[t]*64 + ld_c8[t];
                CP16(kb + so,         g_Kh + go);
                CP16(kb + 9216u + so, g_Kl + go);
                CP16(vb + so,         g_Vh + go);
                CP16(vb + 9216u + so, g_Vl + go);
            }
        }
        CP_COMMIT();
        CP_WAIT1();
        __syncthreads();   // (A)

        __nv_bfloat16* sKh = (__nv_bfloat16*)(sm + ATT_K + buf*18432);
        __nv_bfloat16* sKl = (__nv_bfloat16*)(sm + ATT_K + buf*18432 + 9216);
        __nv_bfloat16* sVh = (__nv_bfloat16*)(sm + ATT_V + buf*18432);
        __nv_bfloat16* sVl = (__nv_bfloat16*)(sm + ATT_V + buf*18432 + 9216);

        float s[4][2][4];
        #pragma unroll
        for (int i = 0; i < 4; i++)
            #pragma unroll
            for (int j = 0; j < 2; j++)
                #pragma unroll
                for (int e = 0; e < 4; e++) s[i][j][e] = 0.f;

        #pragma unroll
        for (int kk = 0; kk < 64; kk += 16) {
            unsigned a[4][4], bhf[2][2], blf[2][2], t4[4];
            #pragma unroll
            for (int mi = 0; mi < 4; mi++)
                ldsm4(a[mi], smem_u32(&sQh[(wm*64 + mi*16 + l15)*72 + kk + lh8]));
            ldsm4(t4, smem_u32(&sKh[(wn*16 + bn)*72 + kk + bk8]));
            bhf[0][0]=t4[0]; bhf[0][1]=t4[1]; bhf[1][0]=t4[2]; bhf[1][1]=t4[3];
            ldsm4(t4, smem_u32(&sKl[(wn*16 + bn)*72 + kk + bk8]));
            blf[0][0]=t4[0]; blf[0][1]=t4[1]; blf[1][0]=t4[2]; blf[1][1]=t4[3];
            #pragma unroll
            for (int mi = 0; mi < 4; mi++)
                #pragma unroll
                for (int ni = 0; ni < 2; ni++) mma_bf(s[mi][ni], a[mi], bhf[ni]);
            #pragma unroll
            for (int mi = 0; mi < 4; mi++)
                #pragma unroll
                for (int ni = 0; ni < 2; ni++) mma_bf(s[mi][ni], a[mi], blf[ni]);
            #pragma unroll
            for (int mi = 0; mi < 4; mi++)
                ldsm4(a[mi], smem_u32(&sQl[(wm*64 + mi*16 + l15)*72 + kk + lh8]));
            #pragma unroll
            for (int mi = 0; mi < 4; mi++)
                #pragma unroll
                for (int ni = 0; ni < 2; ni++) mma_bf(s[mi][ni], a[mi], bhf[ni]);
        }

        const int k0g = kt << 6;
        #pragma unroll
        for (int mi = 0; mi < 4; mi++) {
            float sumA = 0.f, sumB = 0.f;
            const int rowA = wm*64 + mi*16 + rA0;
            #pragma unroll
            for (int ni = 0; ni < 2; ni++) {
                const int col = wn*16 + ni*8 + c2;
                const bool v0 = (k0g + col)     < nv;
                const bool v1 = (k0g + col + 1) < nv;
                float p00 = v0 ? __expf(s[mi][ni][0]*SCALE_) : 0.f;
                float p01 = v1 ? __expf(s[mi][ni][1]*SCALE_) : 0.f;
                float p10 = v0 ? __expf(s[mi][ni][2]*SCALE_) : 0.f;
                float p11 = v1 ? __expf(s[mi][ni][3]*SCALE_) : 0.f;
                sumA += p00 + p01;  sumB += p10 + p11;
                __nv_bfloat16 h00 = __float2bfloat16_rn(p00);
                __nv_bfloat16 h01 = __float2bfloat16_rn(p01);
                __nv_bfloat16 h10 = __float2bfloat16_rn(p10);
                __nv_bfloat16 h11 = __float2bfloat16_rn(p11);
                __nv_bfloat162 vh0; vh0.x=h00; vh0.y=h01;
                __nv_bfloat162 vh1; vh1.x=h10; vh1.y=h11;
                __nv_bfloat162 vl0, vl1;
                vl0.x = __float2bfloat16_rn(p00 - __bfloat162float(h00));
                vl0.y = __float2bfloat16_rn(p01 - __bfloat162float(h01));
                vl1.x = __float2bfloat16_rn(p10 - __bfloat162float(h10));
                vl1.y = __float2bfloat16_rn(p11 - __bfloat162float(h11));
                *(__nv_bfloat162*)(sPh + rowA*72 + col)      = vh0;
                *(__nv_bfloat162*)(sPh + (rowA+8)*72 + col)  = vh1;
                *(__nv_bfloat162*)(sPl + rowA*72 + col)      = vl0;
                *(__nv_bfloat162*)(sPl + (rowA+8)*72 + col)  = vl1;
            }
            sumA += __shfl_xor_sync(0xffffffffu, sumA, 1);
            sumA += __shfl_xor_sync(0xffffffffu, sumA, 2);
            sumB += __shfl_xor_sync(0xffffffffu, sumB, 1);
            sumB += __shfl_xor_sync(0xffffffffu, sumB, 2);
            if ((lane & 3) == 0) {
                psum[rowA*4 + wn]     = sumA;
                psum[(rowA+8)*4 + wn] = sumB;
            }
        }
        __syncthreads();   // (B)

        if (tid < 128)
            l_s[tid] += psum[tid*4+0] + psum[tid*4+1] + psum[tid*4+2] + psum[tid*4+3];

        #pragma unroll
        for (int kk = 0; kk < 64; kk += 16) {
            unsigned pa[4][4], vhf[2][2], vlf[2][2], t4[4];
            #pragma unroll
            for (int mi = 0; mi < 4; mi++)
                ldsm4(pa[mi], smem_u32(&sPh[(wm*64 + mi*16 + l15)*72 + kk + lh8]));
            ldsm4t(t4, smem_u32(&sVh[(kk + l15)*72 + wn*16 + lh8]));
            vhf[0][0]=t4[0]; vhf[0][1]=t4[1]; vhf[1][0]=t4[2]; vhf[1][1]=t4[3];
            ldsm4t(t4, smem_u32(&sVl[(kk + l15)*72 + wn*16 + lh8]));
            vlf[0][0]=t4[0]; vlf[0][1]=t4[1]; vlf[1][0]=t4[2]; vlf[1][1]=t4[3];
            #pragma unroll
            for (int mi = 0; mi < 4; mi++)
                #pragma unroll
                for (int ni = 0; ni < 2; ni++) mma_bf(o[mi][ni], pa[mi], vhf[ni]);
            #pragma unroll
            for (int mi = 0; mi < 4; mi++)
                #pragma unroll
                for (int ni = 0; ni < 2; ni++) mma_bf(o[mi][ni], pa[mi], vlf[ni]);
            #pragma unroll
            for (int mi = 0; mi < 4; mi++)
                ldsm4(pa[mi], smem_u32(&sPl[(wm*64 + mi*16 + l15)*72 + kk + lh8]));
            #pragma unroll
            for (int mi = 0; mi < 4; mi++)
                #pragma unroll
                for (int ni = 0; ni < 2; ni++) mma_bf(o[mi][ni], pa[mi], vhf[ni]);
        }
        __syncthreads();   // (C)
    }

    #pragma unroll
    for (int mi = 0; mi < 4; mi++) {
        const int rowA = wm*64 + mi*16 + rA0, rowB = rowA + 8;
        const float invA = 1.f / l_s[rowA], invB = 1.f / l_s[rowB];
        #pragma unroll
        for (int ni = 0; ni < 2; ni++) {
            const int col = wn*16 + ni*8 + c2;
            float2 w0; w0.x = o[mi][ni][0]*invA; w0.y = o[mi][ni][1]*invA;
            float2 w1; w1.x = o[mi][ni][2]*invB; w1.y = o[mi][ni][3]*invB;
            *(float2*)(g_CTX + (size_t)(bb*T_ + qt0 + rowA)*D_ + hh*64 + col) = w0;
            *(float2*)(g_CTX + (size_t)(bb*T_ + qt0 + rowB)*D_ + hh*64 + col) = w1;
        }
    }
}

// ============================================================================
extern "C" void kernel_launch(void* const* d_in, const int* in_sizes, int n_in,
                              void* d_out, int out_size)
{
    const float* q  = (const float*)d_in[0];
    const float* k  = (const float*)d_in[1];
    const float* v  = (const float*)d_in[2];
    const int*  mk  = (const int*)  d_in[3];
    const float* Wq = (const float*)d_in[4];
    const float* bq = (const float*)d_in[5];
    const float* Wk = (const float*)d_in[6];
    const float* bk = (const float*)d_in[7];
    const float* Wv = (const float*)d_in[8];
    const float* bv = (const float*)d_in[9];
    const float* Wo = (const float*)d_in[10];
    const float* bo = (const float*)d_in[11];
    float* out = (float*)d_out;

    float* pCTX;
    __nv_bfloat16 *pAh, *pAl, *pWh, *pWl, *pQh, *pQl, *pKh, *pKl, *pVh, *pVl;
    cudaGetSymbolAddress((void**)&pCTX, g_CTX);
    cudaGetSymbolAddress((void**)&pAh, g_Ah);
    cudaGetSymbolAddress((void**)&pAl, g_Al);
    cudaGetSymbolAddress((void**)&pWh, g_Wh);
    cudaGetSymbolAddress((void**)&pWl, g_Wl);
    cudaGetSymbolAddress((void**)&pQh, g_Qh);
    cudaGetSymbolAddress((void**)&pQl, g_Ql);
    cudaGetSymbolAddress((void**)&pKh, g_Kh);
    cudaGetSymbolAddress((void**)&pKl, g_Kl);
    cudaGetSymbolAddress((void**)&pVh, g_Vh);
    cudaGetSymbolAddress((void**)&pVl, g_Vl);

    cudaFuncSetAttribute(gemm_qkv,
                         cudaFuncAttributeMaxDynamicSharedMemorySize, GEMM_SMEM);
    cudaFuncSetAttribute(gemm_out,
                         cudaFuncAttributeMaxDynamicSharedMemorySize, GEMM_SMEM);
    cudaFuncSetAttribute(attn_mma,
                         cudaFuncAttributeMaxDynamicSharedMemorySize, ATT_SMEM);

    dim3 blk(256);

    scan_mask<<<B_, 1024>>>(mk);
    convW4<<<dim3(1024, 4), blk>>>(Wq, Wk, Wv, Wo, pWh, pWl);
    convA3<<<dim3(4096, 3), blk>>>(q, k, v, pAh, pAl);
    gemm_qkv<<<dim3(8, 32, 3), blk, GEMM_SMEM>>>(
        pAh, pAl, pWh, pWl, bq, bk, bv, pQh, pQl, pKh, pKl, pVh, pVl);
    attn_mma<<<dim3(16, 16, 2), blk, ATT_SMEM>>>();
    convA1<<<4096, blk>>>(pCTX, pAh, pAl);
    gemm_out<<<dim3(8, 32), blk, GEMM_SMEM>>>(pAh, pAl, pWh, pWl, bo, out);
}

// round 10
// speedup vs baseline: 1.3051x; 1.3051x over previous
#include <cuda_runtime.h>
#include <cuda_fp16.h>
#include <math.h>
#include <stdint.h>

#define B_ 2
#define T_ 2048
#define D_ 1024
#define H_ 16
#define DH_ 64
#define SCALE_ 0.03125f     /* 1/sqrt(1024) exactly */

#define ASTRIDE ((size_t)4096*1024)
#define WSTRIDE ((size_t)1024*1024)

// ============================================================================
// Scratch (static device globals — no allocation in kernel_launch)
// ============================================================================
__device__ float g_CTX[(size_t)B_*T_*D_];
__device__ __half g_Ah[3*ASTRIDE];              // A hi only (2-stream GEMM)
__device__ __half g_Wh[4*WSTRIDE];
__device__ __half g_Wl[4*WSTRIDE];
__device__ __half g_Qh[(size_t)B_*H_*T_*DH_];
__device__ __half g_Ql[(size_t)B_*H_*T_*DH_];
__device__ __half g_Kh[(size_t)B_*H_*T_*DH_];   // compacted
__device__ __half g_Kl[(size_t)B_*H_*T_*DH_];   // compacted
__device__ __half g_Vh[(size_t)B_*H_*T_*DH_];   // compacted
__device__ __half g_Vl[(size_t)B_*H_*T_*DH_];   // compacted
__device__ int g_pos[B_*T_];
__device__ int g_cnt[B_];

// ============================================================================
// mma.sync / ldmatrix / cp.async helpers (base-target PTX)
// ============================================================================
__device__ __forceinline__ unsigned smem_u32(const void* p) {
    unsigned a;
    asm("{ .reg .u64 t; cvta.to.shared.u64 t, %1; cvt.u32.u64 %0, t; }"
        : "=r"(a) : "l"(p));
    return a;
}
__device__ __forceinline__ void mma_fp(float* c, const unsigned* a, const unsigned* b) {
    asm volatile(
        "mma.sync.aligned.m16n8k16.row.col.f32.f16.f16.f32 "
        "{%0,%1,%2,%3}, {%4,%5,%6,%7}, {%8,%9}, {%0,%1,%2,%3};"
        : "+f"(c[0]), "+f"(c[1]), "+f"(c[2]), "+f"(c[3])
        : "r"(a[0]), "r"(a[1]), "r"(a[2]), "r"(a[3]), "r"(b[0]), "r"(b[1]));
}
__device__ __forceinline__ void ldsm4(unsigned* r, unsigned a) {
    asm volatile("ldmatrix.sync.aligned.m8n8.x4.shared.b16 {%0,%1,%2,%3}, [%4];"
        : "=r"(r[0]), "=r"(r[1]), "=r"(r[2]), "=r"(r[3]) : "r"(a));
}
__device__ __forceinline__ void ldsm4t(unsigned* r, unsigned a) {
    asm volatile("ldmatrix.sync.aligned.m8n8.x4.trans.shared.b16 {%0,%1,%2,%3}, [%4];"
        : "=r"(r[0]), "=r"(r[1]), "=r"(r[2]), "=r"(r[3]) : "r"(a));
}
#define CP16(dst_u32, src_ptr) \
    asm volatile("cp.async.cg.shared.global [%0], [%1], 16;" \
        :: "r"(dst_u32), "l"(src_ptr) : "memory")
#define CP_COMMIT() asm volatile("cp.async.commit_group;" ::: "memory")
#define CP_WAIT1()  asm volatile("cp.async.wait_group 1;"  ::: "memory")

// ============================================================================
// scan_mask
// ============================================================================
__global__ void __launch_bounds__(1024) scan_mask(const int* __restrict__ mask)
{
    __shared__ int ps[1024];
    const int b = blockIdx.x, i = threadIdx.x;
    const int a0 = (mask[b*T_ + 2*i]     != 0);
    const int a1 = (mask[b*T_ + 2*i + 1] != 0);
    ps[i] = a0 + a1;
    __syncthreads();
    for (int off = 1; off < 1024; off <<= 1) {
        int v = ps[i] + ((i >= off) ? ps[i - off] : 0);
        __syncthreads();
        ps[i] = v;
        __syncthreads();
    }
    const int excl = (i > 0) ? ps[i-1] : 0;
    g_pos[b*T_ + 2*i]     = a0 ? excl : -1;
    g_pos[b*T_ + 2*i + 1] = a1 ? (excl + a0) : -1;
    if (i == 1023) g_cnt[b] = ps[1023];
}

// ============================================================================
// conversions: fp32 -> fp16 (A: hi only; W: hi+lo)
// ============================================================================
__global__ void __launch_bounds__(256) convA3(
    const float* __restrict__ q, const float* __restrict__ k,
    const float* __restrict__ v, __half* __restrict__ hiB)
{
    const int z = blockIdx.y;
    const float* src = (z == 0) ? q : (z == 1) ? k : v;
    int i = blockIdx.x * 256 + threadIdx.x;
    float4 w = ((const float4*)src)[i];
    __half2 a; a.x = __float2half_rn(w.x); a.y = __float2half_rn(w.y);
    __half2 b; b.x = __float2half_rn(w.z); b.y = __float2half_rn(w.w);
    __half* hi = hiB + z*ASTRIDE;
    ((__half2*)hi)[2*i]   = a;
    ((__half2*)hi)[2*i+1] = b;
}

__global__ void __launch_bounds__(256) convA1(
    const float* __restrict__ x, __half* __restrict__ hi)
{
    int i = blockIdx.x * 256 + threadIdx.x;
    float4 w = ((const float4*)x)[i];
    __half2 a; a.x = __float2half_rn(w.x); a.y = __float2half_rn(w.y);
    __half2 b; b.x = __float2half_rn(w.z); b.y = __float2half_rn(w.w);
    ((__half2*)hi)[2*i]   = a;
    ((__half2*)hi)[2*i+1] = b;
}

__global__ void __launch_bounds__(256) convW4(
    const float* __restrict__ wq, const float* __restrict__ wk,
    const float* __restrict__ wv, const float* __restrict__ wo,
    __half* __restrict__ hiB, __half* __restrict__ loB)
{
    const int z = blockIdx.y;
    const float* src = (z == 0) ? wq : (z == 1) ? wk : (z == 2) ? wv : wo;
    int i = blockIdx.x * 256 + threadIdx.x;
    float4 v = ((const float4*)src)[i];
    __half h0 = __float2half_rn(v.x);
    __half h1 = __float2half_rn(v.y);
    __half h2 = __float2half_rn(v.z);
    __half h3 = __float2half_rn(v.w);
    __half2 ha; ha.x = h0; ha.y = h1;
    __half2 hb; hb.x = h2; hb.y = h3;
    __half2 la, lb;
    la.x = __float2half_rn(v.x - __half2float(h0));
    la.y = __float2half_rn(v.y - __half2float(h1));
    lb.x = __float2half_rn(v.z - __half2float(h2));
    lb.y = __float2half_rn(v.w - __half2float(h3));
    __half* hi = hiB + z*WSTRIDE;
    __half* lo = loB + z*WSTRIDE;
    ((__half2*)hi)[2*i]   = ha;
    ((__half2*)hi)[2*i+1] = hb;
    ((__half2*)lo)[2*i]   = la;
    ((__half2*)lo)[2*i+1] = lb;
}

// ============================================================================
// GEMM core: Y = Ah @ (Wh + Wl) + bias   (fp16 2-stream)
// cp.async 3-stage pipeline. Stage: Ah[128][40]=10240B, Wh[32][136]=8704B,
// Wl=8704B -> GST=27648.
// mode 0: Q proj -> fp16 hi+lo scatter [B,H,T,64]
// mode 1: K/V proj -> fp16 hi+lo scatter to COMPACTED rows
// mode 2: dense fp32 out
// ============================================================================
#define GST 27648
#define G_WH_OFF 10240
#define G_WL_OFF 18944
#define GEMM_SMEM (3*GST)

__device__ __forceinline__ void gemm_core(
    char* gsm,
    const __half* __restrict__ Ah,
    const __half* __restrict__ Wh, const __half* __restrict__ Wl,
    const float* __restrict__ bias,
    float* __restrict__ Yf,
    __half* __restrict__ Yh, __half* __restrict__ Yl,
    int mode, int m0, int n0)
{
    const int tid = threadIdx.x, lane = tid & 31, wid = tid >> 5;
    const int wm = wid >> 2, wn = wid & 3;

    float c[4][4][4];
    #pragma unroll
    for (int i = 0; i < 4; i++)
        #pragma unroll
        for (int j = 0; j < 4; j++)
            #pragma unroll
            for (int e = 0; e < 4; e++) c[i][j][e] = 0.f;

    const int l15 = lane & 15, lh8 = (lane >> 4) << 3;
    const unsigned smb = smem_u32(gsm);

    int a_row[2], a_c8[2], w_row[2], w_c8[2];
    #pragma unroll
    for (int t = 0; t < 2; t++) {
        int ch = tid + t*256;
        a_row[t] = ch >> 2;  a_c8[t] = (ch & 3) << 3;
        w_row[t] = ch >> 4;  w_c8[t] = (ch & 15) << 3;
    }

    auto issue = [&](int s, int k0) {
        const unsigned base = smb + s*GST;
        #pragma unroll
        for (int t = 0; t < 2; t++) {
            unsigned aso = base + (unsigned)(a_row[t]*80 + a_c8[t]*2);
            size_t ago = (size_t)(m0 + a_row[t])*1024 + k0 + a_c8[t];
            CP16(aso, Ah + ago);
            unsigned wso = base + G_WH_OFF + (unsigned)(w_row[t]*272 + w_c8[t]*2);
            size_t wgo = (size_t)(k0 + w_row[t])*1024 + n0 + w_c8[t];
            CP16(wso,                       Wh + wgo);
            CP16(wso + (G_WL_OFF-G_WH_OFF), Wl + wgo);
        }
    };

    issue(0, 0);
    CP_COMMIT();
    issue(1, 32);
    CP_COMMIT();

    for (int kc = 0; kc < 32; kc++) {
        CP_WAIT1();
        __syncthreads();
        if (kc + 2 < 32) issue((kc + 2) % 3, (kc + 2) << 5);
        CP_COMMIT();

        const int buf = kc % 3;
        const __half* sAh = (const __half*)(gsm + buf*GST);
        const __half* sWh = (const __half*)(gsm + buf*GST + G_WH_OFF);
        const __half* sWl = (const __half*)(gsm + buf*GST + G_WL_OFF);

        #pragma unroll
        for (int kk = 0; kk < 32; kk += 16) {
            unsigned a[4][4], bh_[4][2], bl_[4][2], t4[4];
            #pragma unroll
            for (int mi = 0; mi < 4; mi++)
                ldsm4(a[mi], smem_u32(&sAh[(wm*64 + mi*16 + l15)*40 + kk + lh8]));
            #pragma unroll
            for (int p = 0; p < 2; p++) {
                ldsm4t(t4, smem_u32(&sWh[(kk + l15)*136 + wn*32 + p*16 + lh8]));
                bh_[2*p][0]=t4[0]; bh_[2*p][1]=t4[1];
                bh_[2*p+1][0]=t4[2]; bh_[2*p+1][1]=t4[3];
                ldsm4t(t4, smem_u32(&sWl[(kk + l15)*136 + wn*32 + p*16 + lh8]));
                bl_[2*p][0]=t4[0]; bl_[2*p][1]=t4[1];
                bl_[2*p+1][0]=t4[2]; bl_[2*p+1][1]=t4[3];
            }
            #pragma unroll
            for (int mi = 0; mi < 4; mi++)
                #pragma unroll
                for (int ni = 0; ni < 4; ni++) mma_fp(c[mi][ni], a[mi], bh_[ni]);
            #pragma unroll
            for (int mi = 0; mi < 4; mi++)
                #pragma unroll
                for (int ni = 0; ni < 4; ni++) mma_fp(c[mi][ni], a[mi], bl_[ni]);
        }
    }

    // Epilogue
    const int rA = lane >> 2, c2 = (lane & 3) << 1;
    #pragma unroll
    for (int mi = 0; mi < 4; mi++) {
        const int rowA = m0 + wm*64 + mi*16 + rA;
        const int rowB = rowA + 8;
        int pA = rowA & (T_-1), pB = rowB & (T_-1);
        if (mode == 1) { pA = g_pos[rowA]; pB = g_pos[rowB]; }
        #pragma unroll
        for (int ni = 0; ni < 4; ni++) {
            const int col = n0 + wn*32 + ni*8 + c2;
            float2 bb = *(const float2*)(bias + col);
            float v00 = c[mi][ni][0] + bb.x, v01 = c[mi][ni][1] + bb.y;
            float v10 = c[mi][ni][2] + bb.x, v11 = c[mi][ni][3] + bb.y;
            if (mode == 2) {
                float2 w0; w0.x = v00; w0.y = v01;
                float2 w1; w1.x = v10; w1.y = v11;
                *(float2*)(Yf + (size_t)rowA * 1024 + col) = w0;
                *(float2*)(Yf + (size_t)rowB * 1024 + col) = w1;
            } else {
                const int hh = col >> 6, dd = col & 63;
                const int bA = rowA >> 11, bB = rowB >> 11;
                __half h00 = __float2half_rn(v00);
                __half h01 = __float2half_rn(v01);
                __half h10 = __float2half_rn(v10);
                __half h11 = __float2half_rn(v11);
                __half2 ph0; ph0.x=h00; ph0.y=h01;
                __half2 ph1; ph1.x=h10; ph1.y=h11;
                __half2 pl0, pl1;
                pl0.x = __float2half_rn(v00 - __half2float(h00));
                pl0.y = __float2half_rn(v01 - __half2float(h01));
                pl1.x = __float2half_rn(v10 - __half2float(h10));
                pl1.y = __float2half_rn(v11 - __half2float(h11));
                if (pA >= 0) {
                    size_t oA = (((size_t)(bA*H_ + hh))*T_ + pA)*64 + dd;
                    *(__half2*)(Yh + oA) = ph0;
                    *(__half2*)(Yl + oA) = pl0;
                }
                if (pB >= 0) {
                    size_t oB = (((size_t)(bB*H_ + hh))*T_ + pB)*64 + dd;
                    *(__half2*)(Yh + oB) = ph1;
                    *(__half2*)(Yl + oB) = pl1;
                }
            }
        }
    }
}

__global__ void __launch_bounds__(256, 2) gemm_qkv(
    const __half* __restrict__ AhB,
    const __half* __restrict__ WhB, const __half* __restrict__ WlB,
    const float* __restrict__ bq, const float* __restrict__ bk,
    const float* __restrict__ bv,
    __half* __restrict__ Qh, __half* __restrict__ Ql,
    __half* __restrict__ Kh, __half* __restrict__ Kl,
    __half* __restrict__ Vh, __half* __restrict__ Vl)
{
    extern __shared__ __align__(16) char gsm[];
    const int z = blockIdx.z;
    const float* bias = (z == 0) ? bq : (z == 1) ? bk : bv;
    __half* Yh = (z == 0) ? Qh : (z == 1) ? Kh : Vh;
    __half* Yl = (z == 0) ? Ql : (z == 1) ? Kl : Vl;
    gemm_core(gsm, AhB + z*ASTRIDE, WhB + z*WSTRIDE, WlB + z*WSTRIDE, bias,
              nullptr, Yh, Yl, (z == 0) ? 0 : 1,
              blockIdx.y << 7, blockIdx.x << 7);
}

__global__ void __launch_bounds__(256, 2) gemm_out(
    const __half* __restrict__ AhB,
    const __half* __restrict__ WhB, const __half* __restrict__ WlB,
    const float* __restrict__ bo, float* __restrict__ out)
{
    extern __shared__ __align__(16) char gsm[];
    gemm_core(gsm, AhB, WhB + 3*WSTRIDE, WlB + 3*WSTRIDE, bo,
              out, nullptr, nullptr, 2, blockIdx.y << 7, blockIdx.x << 7);
}

// ============================================================================
// Flash attention (fp16): S = Qh·Kh + Qh·Kl + Ql·Kh (3-stream);
// PV = Ph·Vh + Ph·Vl (2-stream, Pl dropped). Compacted keys, cp.async 2-buf.
// ============================================================================
#define ATT_QH   0
#define ATT_QL   18432
#define ATT_K    36864
#define ATT_V    73728
#define ATT_PH   110592
#define ATT_PSUM 129024
#define ATT_LS   131072
#define ATT_SMEM 131584

__global__ void __launch_bounds__(256) attn_mma()
{
    extern __shared__ __align__(16) char sm[];
    __half* sQh = (__half*)(sm + ATT_QH);
    __half* sQl = (__half*)(sm + ATT_QL);
    __half* sPh = (__half*)(sm + ATT_PH);
    float* psum = (float*)(sm + ATT_PSUM);
    float* l_s  = (float*)(sm + ATT_LS);

    const int tid = threadIdx.x, lane = tid & 31, wid = tid >> 5;
    const int wm = wid >> 2, wn = wid & 3;
    const int qt0 = blockIdx.x << 7;
    const int hh = blockIdx.y, bb = blockIdx.z;
    const size_t base = ((size_t)(bb*H_ + hh)) * T_ * DH_;
    const int nv = g_cnt[bb];
    const int nt = (nv + 63) >> 6;

    const int r = tid >> 1, cofs = (tid & 1) << 5;
    const int l15 = lane & 15, lh8 = (lane >> 4) << 3;
    const int bn  = (lane & 7) + ((lane >> 4) << 3), bk8 = ((lane >> 3) & 1) << 3;
    const int rA0 = lane >> 2, c2 = (lane & 3) << 1;

    const unsigned smK = smem_u32(sm + ATT_K);
    const unsigned smV = smem_u32(sm + ATT_V);

    int ld_row[2], ld_c8[2];
    #pragma unroll
    for (int t = 0; t < 2; t++) {
        int ch = tid + t*256;
        ld_row[t] = ch >> 3;
        ld_c8[t]  = (ch & 7) << 3;
    }

    {
        const uint4* s1 = (const uint4*)(g_Qh + base + (size_t)(qt0 + r)*64 + cofs);
        uint4* d1 = (uint4*)(sQh + r*72 + cofs);
        d1[0]=s1[0]; d1[1]=s1[1]; d1[2]=s1[2]; d1[3]=s1[3];
        const uint4* s2 = (const uint4*)(g_Ql + base + (size_t)(qt0 + r)*64 + cofs);
        uint4* d2 = (uint4*)(sQl + r*72 + cofs);
        d2[0]=s2[0]; d2[1]=s2[1]; d2[2]=s2[2]; d2[3]=s2[3];
    }
    if (tid < 128) l_s[tid] = 0.f;

    float o[4][2][4];
    #pragma unroll
    for (int i = 0; i < 4; i++)
        #pragma unroll
        for (int j = 0; j < 2; j++)
            #pragma unroll
            for (int e = 0; e < 4; e++) o[i][j][e] = 0.f;

    #pragma unroll
    for (int t = 0; t < 2; t++) {
        unsigned so = (unsigned)((ld_row[t]*72 + ld_c8[t]) * 2);
        size_t go = base + (size_t)ld_row[t]*64 + ld_c8[t];
        CP16(smK + so,         g_Kh + go);
        CP16(smK + 9216u + so, g_Kl + go);
        CP16(smV + so,         g_Vh + go);
        CP16(smV + 9216u + so, g_Vl + go);
    }
    CP_COMMIT();

    for (int kt = 0; kt < nt; kt++) {
        const int buf = kt & 1;
        if (kt + 1 < nt) {
            const size_t gofs = base + ((size_t)(kt+1) << 6) * 64;
            const unsigned kb = smK + (buf ^ 1) * 18432u;
            const unsigned vb = smV + (buf ^ 1) * 18432u;
            #pragma unroll
            for (int t = 0; t < 2; t++) {
                unsigned so = (unsigned)((ld_row[t]*72 + ld_c8[t]) * 2);
                size_t go = gofs + (size_t)ld_row[t]*64 + ld_c8[t];
                CP16(kb + so,         g_Kh + go);
                CP16(kb + 9216u + so, g_Kl + go);
                CP16(vb + so,         g_Vh + go);
                CP16(vb + 9216u + so, g_Vl + go);
            }
        }
        CP_COMMIT();
        CP_WAIT1();
        __syncthreads();   // (A)

        __half* sKh = (__half*)(sm + ATT_K + buf*18432);
        __half* sKl = (__half*)(sm + ATT_K + buf*18432 + 9216);
        __half* sVh = (__half*)(sm + ATT_V + buf*18432);
        __half* sVl = (__half*)(sm + ATT_V + buf*18432 + 9216);

        // ---- S = Qh·Kh + Qh·Kl + Ql·Kh ----
        float s[4][2][4];
        #pragma unroll
        for (int i = 0; i < 4; i++)
            #pragma unroll
            for (int j = 0; j < 2; j++)
                #pragma unroll
                for (int e = 0; e < 4; e++) s[i][j][e] = 0.f;

        #pragma unroll
        for (int kk = 0; kk < 64; kk += 16) {
            unsigned a[4][4], bhf[2][2], blf[2][2], t4[4];
            #pragma unroll
            for (int mi = 0; mi < 4; mi++)
                ldsm4(a[mi], smem_u32(&sQh[(wm*64 + mi*16 + l15)*72 + kk + lh8]));
            ldsm4(t4, smem_u32(&sKh[(wn*16 + bn)*72 + kk + bk8]));
            bhf[0][0]=t4[0]; bhf[0][1]=t4[1]; bhf[1][0]=t4[2]; bhf[1][1]=t4[3];
            ldsm4(t4, smem_u32(&sKl[(wn*16 + bn)*72 + kk + bk8]));
            blf[0][0]=t4[0]; blf[0][1]=t4[1]; blf[1][0]=t4[2]; blf[1][1]=t4[3];
            #pragma unroll
            for (int mi = 0; mi < 4; mi++)
                #pragma unroll
                for (int ni = 0; ni < 2; ni++) mma_fp(s[mi][ni], a[mi], bhf[ni]);
            #pragma unroll
            for (int mi = 0; mi < 4; mi++)
                #pragma unroll
                for (int ni = 0; ni < 2; ni++) mma_fp(s[mi][ni], a[mi], blf[ni]);
            #pragma unroll
            for (int mi = 0; mi < 4; mi++)
                ldsm4(a[mi], smem_u32(&sQl[(wm*64 + mi*16 + l15)*72 + kk + lh8]));
            #pragma unroll
            for (int mi = 0; mi < 4; mi++)
                #pragma unroll
                for (int ni = 0; ni < 2; ni++) mma_fp(s[mi][ni], a[mi], bhf[ni]);
        }

        // ---- p = (col valid) ? exp(s*scale) : 0; row sums; write Ph ----
        const int k0g = kt << 6;
        #pragma unroll
        for (int mi = 0; mi < 4; mi++) {
            float sumA = 0.f, sumB = 0.f;
            const int rowA = wm*64 + mi*16 + rA0;
            #pragma unroll
            for (int ni = 0; ni < 2; ni++) {
                const int col = wn*16 + ni*8 + c2;
                const bool v0 = (k0g + col)     < nv;
                const bool v1 = (k0g + col + 1) < nv;
                float p00 = v0 ? __expf(s[mi][ni][0]*SCALE_) : 0.f;
                float p01 = v1 ? __expf(s[mi][ni][1]*SCALE_) : 0.f;
                float p10 = v0 ? __expf(s[mi][ni][2]*SCALE_) : 0.f;
                float p11 = v1 ? __expf(s[mi][ni][3]*SCALE_) : 0.f;
                sumA += p00 + p01;  sumB += p10 + p11;
                __half2 vh0; vh0.x = __float2half_rn(p00); vh0.y = __float2half_rn(p01);
                __half2 vh1; vh1.x = __float2half_rn(p10); vh1.y = __float2half_rn(p11);
                *(__half2*)(sPh + rowA*72 + col)      = vh0;
                *(__half2*)(sPh + (rowA+8)*72 + col)  = vh1;
            }
            sumA += __shfl_xor_sync(0xffffffffu, sumA, 1);
            sumA += __shfl_xor_sync(0xffffffffu, sumA, 2);
            sumB += __shfl_xor_sync(0xffffffffu, sumB, 1);
            sumB += __shfl_xor_sync(0xffffffffu, sumB, 2);
            if ((lane & 3) == 0) {
                psum[rowA*4 + wn]     = sumA;
                psum[(rowA+8)*4 + wn] = sumB;
            }
        }
        __syncthreads();   // (B)

        if (tid < 128)
            l_s[tid] += psum[tid*4+0] + psum[tid*4+1] + psum[tid*4+2] + psum[tid*4+3];

        // ---- O += Ph·Vh + Ph·Vl ----
        #pragma unroll
        for (int kk = 0; kk < 64; kk += 16) {
            unsigned pa[4][4], vhf[2][2], vlf[2][2], t4[4];
            #pragma unroll
            for (int mi = 0; mi < 4; mi++)
                ldsm4(pa[mi], smem_u32(&sPh[(wm*64 + mi*16 + l15)*72 + kk + lh8]));
            ldsm4t(t4, smem_u32(&sVh[(kk + l15)*72 + wn*16 + lh8]));
            vhf[0][0]=t4[0]; vhf[0][1]=t4[1]; vhf[1][0]=t4[2]; vhf[1][1]=t4[3];
            ldsm4t(t4, smem_u32(&sVl[(kk + l15)*72 + wn*16 + lh8]));
            vlf[0][0]=t4[0]; vlf[0][1]=t4[1]; vlf[1][0]=t4[2]; vlf[1][1]=t4[3];
            #pragma unroll
            for (int mi = 0; mi < 4; mi++)
                #pragma unroll
                for (int ni = 0; ni < 2; ni++) mma_fp(o[mi][ni], pa[mi], vhf[ni]);
            #pragma unroll
            for (int mi = 0; mi < 4; mi++)
                #pragma unroll
                for (int ni = 0; ni < 2; ni++) mma_fp(o[mi][ni], pa[mi], vlf[ni]);
        }
        __syncthreads();   // (C)
    }

    #pragma unroll
    for (int mi = 0; mi < 4; mi++) {
        const int rowA = wm*64 + mi*16 + rA0, rowB = rowA + 8;
        const float invA = 1.f / l_s[rowA], invB = 1.f / l_s[rowB];
        #pragma unroll
        for (int ni = 0; ni < 2; ni++) {
            const int col = wn*16 + ni*8 + c2;
            float2 w0; w0.x = o[mi][ni][0]*invA; w0.y = o[mi][ni][1]*invA;
            float2 w1; w1.x = o[mi][ni][2]*invB; w1.y = o[mi][ni][3]*invB;
            *(float2*)(g_CTX + (size_t)(bb*T_ + qt0 + rowA)*D_ + hh*64 + col) = w0;
            *(float2*)(g_CTX + (size_t)(bb*T_ + qt0 + rowB)*D_ + hh*64 + col) = w1;
        }
    }
}

// ============================================================================
extern "C" void kernel_launch(void* const* d_in, const int* in_sizes, int n_in,
                              void* d_out, int out_size)
{
    const float* q  = (const float*)d_in[0];
    const float* k  = (const float*)d_in[1];
    const float* v  = (const float*)d_in[2];
    const int*  mk  = (const int*)  d_in[3];
    const float* Wq = (const float*)d_in[4];
    const float* bq = (const float*)d_in[5];
    const float* Wk = (const float*)d_in[6];
    const float* bk = (const float*)d_in[7];
    const float* Wv = (const float*)d_in[8];
    const float* bv = (const float*)d_in[9];
    const float* Wo = (const float*)d_in[10];
    const float* bo = (const float*)d_in[11];
    float* out = (float*)d_out;

    float* pCTX;
    __half *pAh, *pWh, *pWl, *pQh, *pQl, *pKh, *pKl, *pVh, *pVl;
    cudaGetSymbolAddress((void**)&pCTX, g_CTX);
    cudaGetSymbolAddress((void**)&pAh, g_Ah);
    cudaGetSymbolAddress((void**)&pWh, g_Wh);
    cudaGetSymbolAddress((void**)&pWl, g_Wl);
    cudaGetSymbolAddress((void**)&pQh, g_Qh);
    cudaGetSymbolAddress((void**)&pQl, g_Ql);
    cudaGetSymbolAddress((void**)&pKh, g_Kh);
    cudaGetSymbolAddress((void**)&pKl, g_Kl);
    cudaGetSymbolAddress((void**)&pVh, g_Vh);
    cudaGetSymbolAddress((void**)&pVl, g_Vl);

    cudaFuncSetAttribute(gemm_qkv,
                         cudaFuncAttributeMaxDynamicSharedMemorySize, GEMM_SMEM);
    cudaFuncSetAttribute(gemm_out,
                         cudaFuncAttributeMaxDynamicSharedMemorySize, GEMM_SMEM);
    cudaFuncSetAttribute(attn_mma,
                         cudaFuncAttributeMaxDynamicSharedMemorySize, ATT_SMEM);

    dim3 blk(256);

    scan_mask<<<B_, 1024>>>(mk);
    convW4<<<dim3(1024, 4), blk>>>(Wq, Wk, Wv, Wo, pWh, pWl);
    convA3<<<dim3(4096, 3), blk>>>(q, k, v, pAh);
    gemm_qkv<<<dim3(8, 32, 3), blk, GEMM_SMEM>>>(
        pAh, pWh, pWl, bq, bk, bv, pQh, pQl, pKh, pKl, pVh, pVl);
    attn_mma<<<dim3(16, 16, 2), blk, ATT_SMEM>>>();
    convA1<<<4096, blk>>>(pCTX, pAh);
    gemm_out<<<dim3(8, 32), blk, GEMM_SMEM>>>(pAh, pWh, pWl, bo, out);
}

// round 11
// speedup vs baseline: 1.7652x; 1.3526x over previous
#include <cuda_runtime.h>
#include <cuda_fp16.h>
#include <math.h>
#include <stdint.h>

#define B_ 2
#define T_ 2048
#define D_ 1024
#define H_ 16
#define DH_ 64
#define SCALE_ 0.03125f     /* 1/sqrt(1024) exactly */

#define ASTRIDE ((size_t)4096*1024)
#define WSTRIDE ((size_t)1024*1024)

// ============================================================================
// Scratch (static device globals — no allocation in kernel_launch)
// ============================================================================
__device__ float g_CTX[(size_t)B_*T_*D_];
__device__ __half g_Ah[3*ASTRIDE];              // A hi only
__device__ __half g_Wh[4*WSTRIDE];
__device__ __half g_Wl[4*WSTRIDE];              // lo used for V (z=2) and Wo (z=3)
__device__ __half g_Qh[(size_t)B_*H_*T_*DH_];
__device__ __half g_Kh[(size_t)B_*H_*T_*DH_];   // compacted
__device__ __half g_Vh[(size_t)B_*H_*T_*DH_];   // compacted
__device__ __half g_Vl[(size_t)B_*H_*T_*DH_];   // compacted
__device__ int g_pos[B_*T_];
__device__ int g_cnt[B_];

// ============================================================================
// mma.sync / ldmatrix / cp.async helpers (base-target PTX)
// ============================================================================
__device__ __forceinline__ unsigned smem_u32(const void* p) {
    unsigned a;
    asm("{ .reg .u64 t; cvta.to.shared.u64 t, %1; cvt.u32.u64 %0, t; }"
        : "=r"(a) : "l"(p));
    return a;
}
__device__ __forceinline__ void mma_fp(float* c, const unsigned* a, const unsigned* b) {
    asm volatile(
        "mma.sync.aligned.m16n8k16.row.col.f32.f16.f16.f32 "
        "{%0,%1,%2,%3}, {%4,%5,%6,%7}, {%8,%9}, {%0,%1,%2,%3};"
        : "+f"(c[0]), "+f"(c[1]), "+f"(c[2]), "+f"(c[3])
        : "r"(a[0]), "r"(a[1]), "r"(a[2]), "r"(a[3]), "r"(b[0]), "r"(b[1]));
}
__device__ __forceinline__ void ldsm4(unsigned* r, unsigned a) {
    asm volatile("ldmatrix.sync.aligned.m8n8.x4.shared.b16 {%0,%1,%2,%3}, [%4];"
        : "=r"(r[0]), "=r"(r[1]), "=r"(r[2]), "=r"(r[3]) : "r"(a));
}
__device__ __forceinline__ void ldsm4t(unsigned* r, unsigned a) {
    asm volatile("ldmatrix.sync.aligned.m8n8.x4.trans.shared.b16 {%0,%1,%2,%3}, [%4];"
        : "=r"(r[0]), "=r"(r[1]), "=r"(r[2]), "=r"(r[3]) : "r"(a));
}
#define CP16(dst_u32, src_ptr) \
    asm volatile("cp.async.cg.shared.global [%0], [%1], 16;" \
        :: "r"(dst_u32), "l"(src_ptr) : "memory")
#define CP_COMMIT() asm volatile("cp.async.commit_group;" ::: "memory")
#define CP_WAIT1()  asm volatile("cp.async.wait_group 1;"  ::: "memory")

// ============================================================================
// scan_mask
// ============================================================================
__global__ void __launch_bounds__(1024) scan_mask(const int* __restrict__ mask)
{
    __shared__ int ps[1024];
    const int b = blockIdx.x, i = threadIdx.x;
    const int a0 = (mask[b*T_ + 2*i]     != 0);
    const int a1 = (mask[b*T_ + 2*i + 1] != 0);
    ps[i] = a0 + a1;
    __syncthreads();
    for (int off = 1; off < 1024; off <<= 1) {
        int v = ps[i] + ((i >= off) ? ps[i - off] : 0);
        __syncthreads();
        ps[i] = v;
        __syncthreads();
    }
    const int excl = (i > 0) ? ps[i-1] : 0;
    g_pos[b*T_ + 2*i]     = a0 ? excl : -1;
    g_pos[b*T_ + 2*i + 1] = a1 ? (excl + a0) : -1;
    if (i == 1023) g_cnt[b] = ps[1023];
}

// ============================================================================
// conversions: fp32 -> fp16 (A: hi only; W: hi, +lo for z>=2)
// ============================================================================
__global__ void __launch_bounds__(256) convA3(
    const float* __restrict__ q, const float* __restrict__ k,
    const float* __restrict__ v, __half* __restrict__ hiB)
{
    const int z = blockIdx.y;
    const float* src = (z == 0) ? q : (z == 1) ? k : v;
    int i = blockIdx.x * 256 + threadIdx.x;
    float4 w = ((const float4*)src)[i];
    __half2 a; a.x = __float2half_rn(w.x); a.y = __float2half_rn(w.y);
    __half2 b; b.x = __float2half_rn(w.z); b.y = __float2half_rn(w.w);
    __half* hi = hiB + z*ASTRIDE;
    ((__half2*)hi)[2*i]   = a;
    ((__half2*)hi)[2*i+1] = b;
}

__global__ void __launch_bounds__(256) convA1(
    const float* __restrict__ x, __half* __restrict__ hi)
{
    int i = blockIdx.x * 256 + threadIdx.x;
    float4 w = ((const float4*)x)[i];
    __half2 a; a.x = __float2half_rn(w.x); a.y = __float2half_rn(w.y);
    __half2 b; b.x = __float2half_rn(w.z); b.y = __float2half_rn(w.w);
    ((__half2*)hi)[2*i]   = a;
    ((__half2*)hi)[2*i+1] = b;
}

__global__ void __launch_bounds__(256) convW4(
    const float* __restrict__ wq, const float* __restrict__ wk,
    const float* __restrict__ wv, const float* __restrict__ wo,
    __half* __restrict__ hiB, __half* __restrict__ loB)
{
    const int z = blockIdx.y;
    const float* src = (z == 0) ? wq : (z == 1) ? wk : (z == 2) ? wv : wo;
    int i = blockIdx.x * 256 + threadIdx.x;
    float4 v = ((const float4*)src)[i];
    __half h0 = __float2half_rn(v.x);
    __half h1 = __float2half_rn(v.y);
    __half h2 = __float2half_rn(v.z);
    __half h3 = __float2half_rn(v.w);
    __half2 ha; ha.x = h0; ha.y = h1;
    __half2 hb; hb.x = h2; hb.y = h3;
    __half* hi = hiB + z*WSTRIDE;
    ((__half2*)hi)[2*i]   = ha;
    ((__half2*)hi)[2*i+1] = hb;
    if (z >= 2) {   // lo stream needed only for V and Wo
        __half2 la, lb;
        la.x = __float2half_rn(v.x - __half2float(h0));
        la.y = __float2half_rn(v.y - __half2float(h1));
        lb.x = __float2half_rn(v.z - __half2float(h2));
        lb.y = __float2half_rn(v.w - __half2float(h3));
        __half* lo = loB + z*WSTRIDE;
        ((__half2*)lo)[2*i]   = la;
        ((__half2*)lo)[2*i+1] = lb;
    }
}

// ============================================================================
// GEMM core: Y = Ah @ (Wh [+ Wl]) + bias   (fp16, NSTREAM = 1 or 2)
// cp.async 3-stage pipeline. Stage: Ah 10240B, Wh 8704B, Wl 8704B.
// emode 0: Q proj -> Yh only, [B,H,T,64] scatter
// emode 1: K proj -> Yh only, compacted scatter
// emode 2: V proj -> Yh+Yl, compacted scatter
// emode 3: dense fp32 out
// ============================================================================
#define GST 27648
#define G_WH_OFF 10240
#define G_WL_OFF 18944
#define GEMM_SMEM (3*GST)

template<int NSTREAM>
__device__ __forceinline__ void gemm_core(
    char* gsm,
    const __half* __restrict__ Ah,
    const __half* __restrict__ Wh, const __half* __restrict__ Wl,
    const float* __restrict__ bias,
    float* __restrict__ Yf,
    __half* __restrict__ Yh, __half* __restrict__ Yl,
    int emode, int m0, int n0)
{
    const int tid = threadIdx.x, lane = tid & 31, wid = tid >> 5;
    const int wm = wid >> 2, wn = wid & 3;

    float c[4][4][4];
    #pragma unroll
    for (int i = 0; i < 4; i++)
        #pragma unroll
        for (int j = 0; j < 4; j++)
            #pragma unroll
            for (int e = 0; e < 4; e++) c[i][j][e] = 0.f;

    const int l15 = lane & 15, lh8 = (lane >> 4) << 3;
    const unsigned smb = smem_u32(gsm);

    int a_row[2], a_c8[2], w_row[2], w_c8[2];
    #pragma unroll
    for (int t = 0; t < 2; t++) {
        int ch = tid + t*256;
        a_row[t] = ch >> 2;  a_c8[t] = (ch & 3) << 3;
        w_row[t] = ch >> 4;  w_c8[t] = (ch & 15) << 3;
    }

    auto issue = [&](int s, int k0) {
        const unsigned base = smb + s*GST;
        #pragma unroll
        for (int t = 0; t < 2; t++) {
            unsigned aso = base + (unsigned)(a_row[t]*80 + a_c8[t]*2);
            size_t ago = (size_t)(m0 + a_row[t])*1024 + k0 + a_c8[t];
            CP16(aso, Ah + ago);
            unsigned wso = base + G_WH_OFF + (unsigned)(w_row[t]*272 + w_c8[t]*2);
            size_t wgo = (size_t)(k0 + w_row[t])*1024 + n0 + w_c8[t];
            CP16(wso, Wh + wgo);
            if (NSTREAM == 2)
                CP16(wso + (G_WL_OFF-G_WH_OFF), Wl + wgo);
        }
    };

    issue(0, 0);
    CP_COMMIT();
    issue(1, 32);
    CP_COMMIT();

    for (int kc = 0; kc < 32; kc++) {
        CP_WAIT1();
        __syncthreads();
        if (kc + 2 < 32) issue((kc + 2) % 3, (kc + 2) << 5);
        CP_COMMIT();

        const int buf = kc % 3;
        const __half* sAh = (const __half*)(gsm + buf*GST);
        const __half* sWh = (const __half*)(gsm + buf*GST + G_WH_OFF);
        const __half* sWl = (const __half*)(gsm + buf*GST + G_WL_OFF);

        #pragma unroll
        for (int kk = 0; kk < 32; kk += 16) {
            unsigned a[4][4], bh_[4][2], bl_[4][2], t4[4];
            #pragma unroll
            for (int mi = 0; mi < 4; mi++)
                ldsm4(a[mi], smem_u32(&sAh[(wm*64 + mi*16 + l15)*40 + kk + lh8]));
            #pragma unroll
            for (int p = 0; p < 2; p++) {
                ldsm4t(t4, smem_u32(&sWh[(kk + l15)*136 + wn*32 + p*16 + lh8]));
                bh_[2*p][0]=t4[0]; bh_[2*p][1]=t4[1];
                bh_[2*p+1][0]=t4[2]; bh_[2*p+1][1]=t4[3];
                if (NSTREAM == 2) {
                    ldsm4t(t4, smem_u32(&sWl[(kk + l15)*136 + wn*32 + p*16 + lh8]));
                    bl_[2*p][0]=t4[0]; bl_[2*p][1]=t4[1];
                    bl_[2*p+1][0]=t4[2]; bl_[2*p+1][1]=t4[3];
                }
            }
            #pragma unroll
            for (int mi = 0; mi < 4; mi++)
                #pragma unroll
                for (int ni = 0; ni < 4; ni++) mma_fp(c[mi][ni], a[mi], bh_[ni]);
            if (NSTREAM == 2) {
                #pragma unroll
                for (int mi = 0; mi < 4; mi++)
                    #pragma unroll
                    for (int ni = 0; ni < 4; ni++) mma_fp(c[mi][ni], a[mi], bl_[ni]);
            }
        }
    }

    // Epilogue
    const int rA = lane >> 2, c2 = (lane & 3) << 1;
    #pragma unroll
    for (int mi = 0; mi < 4; mi++) {
        const int rowA = m0 + wm*64 + mi*16 + rA;
        const int rowB = rowA + 8;
        int pA = rowA & (T_-1), pB = rowB & (T_-1);
        if (emode == 1 || emode == 2) { pA = g_pos[rowA]; pB = g_pos[rowB]; }
        #pragma unroll
        for (int ni = 0; ni < 4; ni++) {
            const int col = n0 + wn*32 + ni*8 + c2;
            float2 bb = *(const float2*)(bias + col);
            float v00 = c[mi][ni][0] + bb.x, v01 = c[mi][ni][1] + bb.y;
            float v10 = c[mi][ni][2] + bb.x, v11 = c[mi][ni][3] + bb.y;
            if (emode == 3) {
                float2 w0; w0.x = v00; w0.y = v01;
                float2 w1; w1.x = v10; w1.y = v11;
                *(float2*)(Yf + (size_t)rowA * 1024 + col) = w0;
                *(float2*)(Yf + (size_t)rowB * 1024 + col) = w1;
            } else {
                const int hh = col >> 6, dd = col & 63;
                const int bA = rowA >> 11, bB = rowB >> 11;
                __half h00 = __float2half_rn(v00);
                __half h01 = __float2half_rn(v01);
                __half h10 = __float2half_rn(v10);
                __half h11 = __float2half_rn(v11);
                __half2 ph0; ph0.x=h00; ph0.y=h01;
                __half2 ph1; ph1.x=h10; ph1.y=h11;
                if (pA >= 0) {
                    size_t oA = (((size_t)(bA*H_ + hh))*T_ + pA)*64 + dd;
                    *(__half2*)(Yh + oA) = ph0;
                    if (emode == 2) {
                        __half2 pl0;
                        pl0.x = __float2half_rn(v00 - __half2float(h00));
                        pl0.y = __float2half_rn(v01 - __half2float(h01));
                        *(__half2*)(Yl + oA) = pl0;
                    }
                }
                if (pB >= 0) {
                    size_t oB = (((size_t)(bB*H_ + hh))*T_ + pB)*64 + dd;
                    *(__half2*)(Yh + oB) = ph1;
                    if (emode == 2) {
                        __half2 pl1;
                        pl1.x = __float2half_rn(v10 - __half2float(h10));
                        pl1.y = __float2half_rn(v11 - __half2float(h11));
                        *(__half2*)(Yl + oB) = pl1;
                    }
                }
            }
        }
    }
}

__global__ void __launch_bounds__(256, 2) gemm_qkv(
    const __half* __restrict__ AhB,
    const __half* __restrict__ WhB, const __half* __restrict__ WlB,
    const float* __restrict__ bq, const float* __restrict__ bk,
    const float* __restrict__ bv,
    __half* __restrict__ Qh, __half* __restrict__ Kh,
    __half* __restrict__ Vh, __half* __restrict__ Vl)
{
    extern __shared__ __align__(16) char gsm[];
    const int z = blockIdx.z;
    const int m0 = blockIdx.y << 7, n0 = blockIdx.x << 7;
    if (z == 0) {
        gemm_core<1>(gsm, AhB, WhB, nullptr, bq,
                     nullptr, Qh, nullptr, 0, m0, n0);
    } else if (z == 1) {
        gemm_core<1>(gsm, AhB + ASTRIDE, WhB + WSTRIDE, nullptr, bk,
                     nullptr, Kh, nullptr, 1, m0, n0);
    } else {
        gemm_core<2>(gsm, AhB + 2*ASTRIDE, WhB + 2*WSTRIDE, WlB + 2*WSTRIDE, bv,
                     nullptr, Vh, Vl, 2, m0, n0);
    }
}

__global__ void __launch_bounds__(256, 2) gemm_out(
    const __half* __restrict__ AhB,
    const __half* __restrict__ WhB, const __half* __restrict__ WlB,
    const float* __restrict__ bo, float* __restrict__ out)
{
    extern __shared__ __align__(16) char gsm[];
    gemm_core<2>(gsm, AhB, WhB + 3*WSTRIDE, WlB + 3*WSTRIDE, bo,
                 out, nullptr, nullptr, 3, blockIdx.y << 7, blockIdx.x << 7);
}

// ============================================================================
// Flash attention (fp16): S = Qh·Kh (1-stream; exp-arg error ~1e-4);
// PV = Ph·(Vh+Vl) (2-stream). Compacted keys, cp.async 2-buf, 2 CTA/SM.
// ============================================================================
#define ATT_QH   0          /* 128 x 72 half = 18432 */
#define ATT_K    18432      /* 2 bufs x Kh 9216 = 18432 */
#define ATT_V    36864      /* 2 bufs x (Vh+Vl) 18432 = 36864 */
#define ATT_PH   73728      /* 128 x 72 half = 18432 */
#define ATT_PSUM 92160      /* 512 floats */
#define ATT_LS   94208      /* 128 floats */
#define ATT_SMEM 94720

__global__ void __launch_bounds__(256, 2) attn_mma()
{
    extern __shared__ __align__(16) char sm[];
    __half* sQh = (__half*)(sm + ATT_QH);
    __half* sPh = (__half*)(sm + ATT_PH);
    float* psum = (float*)(sm + ATT_PSUM);
    float* l_s  = (float*)(sm + ATT_LS);

    const int tid = threadIdx.x, lane = tid & 31, wid = tid >> 5;
    const int wm = wid >> 2, wn = wid & 3;
    const int qt0 = blockIdx.x << 7;
    const int hh = blockIdx.y, bb = blockIdx.z;
    const size_t base = ((size_t)(bb*H_ + hh)) * T_ * DH_;
    const int nv = g_cnt[bb];
    const int nt = (nv + 63) >> 6;

    const int r = tid >> 1, cofs = (tid & 1) << 5;
    const int l15 = lane & 15, lh8 = (lane >> 4) << 3;
    const int bn  = (lane & 7) + ((lane >> 4) << 3), bk8 = ((lane >> 3) & 1) << 3;
    const int rA0 = lane >> 2, c2 = (lane & 3) << 1;

    const unsigned smK = smem_u32(sm + ATT_K);
    const unsigned smV = smem_u32(sm + ATT_V);

    int ld_row[2], ld_c8[2];
    #pragma unroll
    for (int t = 0; t < 2; t++) {
        int ch = tid + t*256;
        ld_row[t] = ch >> 3;
        ld_c8[t]  = (ch & 7) << 3;
    }

    // Load Q hi (persistent)
    {
        const uint4* s1 = (const uint4*)(g_Qh + base + (size_t)(qt0 + r)*64 + cofs);
        uint4* d1 = (uint4*)(sQh + r*72 + cofs);
        d1[0]=s1[0]; d1[1]=s1[1]; d1[2]=s1[2]; d1[3]=s1[3];
    }
    if (tid < 128) l_s[tid] = 0.f;

    float o[4][2][4];
    #pragma unroll
    for (int i = 0; i < 4; i++)
        #pragma unroll
        for (int j = 0; j < 2; j++)
            #pragma unroll
            for (int e = 0; e < 4; e++) o[i][j][e] = 0.f;

    // Prologue: tile 0 -> buf 0
    #pragma unroll
    for (int t = 0; t < 2; t++) {
        unsigned so = (unsigned)((ld_row[t]*72 + ld_c8[t]) * 2);
        size_t go = base + (size_t)ld_row[t]*64 + ld_c8[t];
        CP16(smK + so,         g_Kh + go);
        CP16(smV + so,         g_Vh + go);
        CP16(smV + 9216u + so, g_Vl + go);
    }
    CP_COMMIT();

    for (int kt = 0; kt < nt; kt++) {
        const int buf = kt & 1;
        if (kt + 1 < nt) {
            const size_t gofs = base + ((size_t)(kt+1) << 6) * 64;
            const unsigned kb = smK + (buf ^ 1) * 9216u;
            const unsigned vb = smV + (buf ^ 1) * 18432u;
            #pragma unroll
            for (int t = 0; t < 2; t++) {
                unsigned so = (unsigned)((ld_row[t]*72 + ld_c8[t]) * 2);
                size_t go = gofs + (size_t)ld_row[t]*64 + ld_c8[t];
                CP16(kb + so,         g_Kh + go);
                CP16(vb + so,         g_Vh + go);
                CP16(vb + 9216u + so, g_Vl + go);
            }
        }
        CP_COMMIT();
        CP_WAIT1();
        __syncthreads();   // (A)

        __half* sKh = (__half*)(sm + ATT_K + buf*9216);
        __half* sVh = (__half*)(sm + ATT_V + buf*18432);
        __half* sVl = (__half*)(sm + ATT_V + buf*18432 + 9216);

        // ---- S = Qh·Kh (single stream) ----
        float s[4][2][4];
        #pragma unroll
        for (int i = 0; i < 4; i++)
            #pragma unroll
            for (int j = 0; j < 2; j++)
                #pragma unroll
                for (int e = 0; e < 4; e++) s[i][j][e] = 0.f;

        #pragma unroll
        for (int kk = 0; kk < 64; kk += 16) {
            unsigned a[4][4], bhf[2][2], t4[4];
            #pragma unroll
            for (int mi = 0; mi < 4; mi++)
                ldsm4(a[mi], smem_u32(&sQh[(wm*64 + mi*16 + l15)*72 + kk + lh8]));
            ldsm4(t4, smem_u32(&sKh[(wn*16 + bn)*72 + kk + bk8]));
            bhf[0][0]=t4[0]; bhf[0][1]=t4[1]; bhf[1][0]=t4[2]; bhf[1][1]=t4[3];
            #pragma unroll
            for (int mi = 0; mi < 4; mi++)
                #pragma unroll
                for (int ni = 0; ni < 2; ni++) mma_fp(s[mi][ni], a[mi], bhf[ni]);
        }

        // ---- p = (col valid) ? exp(s*scale) : 0; row sums; write Ph ----
        const int k0g = kt << 6;
        #pragma unroll
        for (int mi = 0; mi < 4; mi++) {
            float sumA = 0.f, sumB = 0.f;
            const int rowA = wm*64 + mi*16 + rA0;
            #pragma unroll
            for (int ni = 0; ni < 2; ni++) {
                const int col = wn*16 + ni*8 + c2;
                const bool v0 = (k0g + col)     < nv;
                const bool v1 = (k0g + col + 1) < nv;
                float p00 = v0 ? __expf(s[mi][ni][0]*SCALE_) : 0.f;
                float p01 = v1 ? __expf(s[mi][ni][1]*SCALE_) : 0.f;
                float p10 = v0 ? __expf(s[mi][ni][2]*SCALE_) : 0.f;
                float p11 = v1 ? __expf(s[mi][ni][3]*SCALE_) : 0.f;
                sumA += p00 + p01;  sumB += p10 + p11;
                __half2 vh0; vh0.x = __float2half_rn(p00); vh0.y = __float2half_rn(p01);
                __half2 vh1; vh1.x = __float2half_rn(p10); vh1.y = __float2half_rn(p11);
                *(__half2*)(sPh + rowA*72 + col)      = vh0;
                *(__half2*)(sPh + (rowA+8)*72 + col)  = vh1;
            }
            sumA += __shfl_xor_sync(0xffffffffu, sumA, 1);
            sumA += __shfl_xor_sync(0xffffffffu, sumA, 2);
            sumB += __shfl_xor_sync(0xffffffffu, sumB, 1);
            sumB += __shfl_xor_sync(0xffffffffu, sumB, 2);
            if ((lane & 3) == 0) {
                psum[rowA*4 + wn]     = sumA;
                psum[(rowA+8)*4 + wn] = sumB;
            }
        }
        __syncthreads();   // (B)

        if (tid < 128)
            l_s[tid] += psum[tid*4+0] + psum[tid*4+1] + psum[tid*4+2] + psum[tid*4+3];

        // ---- O += Ph·Vh + Ph·Vl ----
        #pragma unroll
        for (int kk = 0; kk < 64; kk += 16) {
            unsigned pa[4][4], vhf[2][2], vlf[2][2], t4[4];
            #pragma unroll
            for (int mi = 0; mi < 4; mi++)
                ldsm4(pa[mi], smem_u32(&sPh[(wm*64 + mi*16 + l15)*72 + kk + lh8]));
            ldsm4t(t4, smem_u32(&sVh[(kk + l15)*72 + wn*16 + lh8]));
            vhf[0][0]=t4[0]; vhf[0][1]=t4[1]; vhf[1][0]=t4[2]; vhf[1][1]=t4[3];
            ldsm4t(t4, smem_u32(&sVl[(kk + l15)*72 + wn*16 + lh8]));
            vlf[0][0]=t4[0]; vlf[0][1]=t4[1]; vlf[1][0]=t4[2]; vlf[1][1]=t4[3];
            #pragma unroll
            for (int mi = 0; mi < 4; mi++)
                #pragma unroll
                for (int ni = 0; ni < 2; ni++) mma_fp(o[mi][ni], pa[mi], vhf[ni]);
            #pragma unroll
            for (int mi = 0; mi < 4; mi++)
                #pragma unroll
                for (int ni = 0; ni < 2; ni++) mma_fp(o[mi][ni], pa[mi], vlf[ni]);
        }
        __syncthreads();   // (C)
    }

    #pragma unroll
    for (int mi = 0; mi < 4; mi++) {
        const int rowA = wm*64 + mi*16 + rA0, rowB = rowA + 8;
        const float invA = 1.f / l_s[rowA], invB = 1.f / l_s[rowB];
        #pragma unroll
        for (int ni = 0; ni < 2; ni++) {
            const int col = wn*16 + ni*8 + c2;
            float2 w0; w0.x = o[mi][ni][0]*invA; w0.y = o[mi][ni][1]*invA;
            float2 w1; w1.x = o[mi][ni][2]*invB; w1.y = o[mi][ni][3]*invB;
            *(float2*)(g_CTX + (size_t)(bb*T_ + qt0 + rowA)*D_ + hh*64 + col) = w0;
            *(float2*)(g_CTX + (size_t)(bb*T_ + qt0 + rowB)*D_ + hh*64 + col) = w1;
        }
    }
}

// ============================================================================
extern "C" void kernel_launch(void* const* d_in, const int* in_sizes, int n_in,
                              void* d_out, int out_size)
{
    const float* q  = (const float*)d_in[0];
    const float* k  = (const float*)d_in[1];
    const float* v  = (const float*)d_in[2];
    const int*  mk  = (const int*)  d_in[3];
    const float* Wq = (const float*)d_in[4];
    const float* bq = (const float*)d_in[5];
    const float* Wk = (const float*)d_in[6];
    const float* bk = (const float*)d_in[7];
    const float* Wv = (const float*)d_in[8];
    const float* bv = (const float*)d_in[9];
    const float* Wo = (const float*)d_in[10];
    const float* bo = (const float*)d_in[11];
    float* out = (float*)d_out;

    float* pCTX;
    __half *pAh, *pWh, *pWl, *pQh, *pKh, *pVh, *pVl;
    cudaGetSymbolAddress((void**)&pCTX, g_CTX);
    cudaGetSymbolAddress((void**)&pAh, g_Ah);
    cudaGetSymbolAddress((void**)&pWh, g_Wh);
    cudaGetSymbolAddress((void**)&pWl, g_Wl);
    cudaGetSymbolAddress((void**)&pQh, g_Qh);
    cudaGetSymbolAddress((void**)&pKh, g_Kh);
    cudaGetSymbolAddress((void**)&pVh, g_Vh);
    cudaGetSymbolAddress((void**)&pVl, g_Vl);

    cudaFuncSetAttribute(gemm_qkv,
                         cudaFuncAttributeMaxDynamicSharedMemorySize, GEMM_SMEM);
    cudaFuncSetAttribute(gemm_out,
                         cudaFuncAttributeMaxDynamicSharedMemorySize, GEMM_SMEM);
    cudaFuncSetAttribute(attn_mma,
                         cudaFuncAttributeMaxDynamicSharedMemorySize, ATT_SMEM);

    dim3 blk(256);

    scan_mask<<<B_, 1024>>>(mk);
    convW4<<<dim3(1024, 4), blk>>>(Wq, Wk, Wv, Wo, pWh, pWl);
    convA3<<<dim3(4096, 3), blk>>>(q, k, v, pAh);
    gemm_qkv<<<dim3(8, 32, 3), blk, GEMM_SMEM>>>(
        pAh, pWh, pWl, bq, bk, bv, pQh, pKh, pVh, pVl);
    attn_mma<<<dim3(16, 16, 2), blk, ATT_SMEM>>>();
    convA1<<<4096, blk>>>(pCTX, pAh);
    gemm_out<<<dim3(8, 32), blk, GEMM_SMEM>>>(pAh, pWh, pWl, bo, out);
}

// round 12
// speedup vs baseline: 2.2113x; 1.2527x over previous
#include <cuda_runtime.h>
#include <cuda_fp16.h>
#include <math.h>
#include <stdint.h>

#define B_ 2
#define T_ 2048
#define D_ 1024
#define H_ 16
#define DH_ 64
#define SCALE_ 0.03125f     /* 1/sqrt(1024) exactly */

#define ASTRIDE ((size_t)4096*1024)
#define WSTRIDE ((size_t)1024*1024)

// ============================================================================
// Scratch (static device globals — no allocation in kernel_launch)
// g_Ah slab 0 is reused by the attention epilogue as the fp16 context buffer.
// ============================================================================
__device__ __half g_Ah[3*ASTRIDE];
__device__ __half g_Wh[4*WSTRIDE];
__device__ __half g_Qh[(size_t)B_*H_*T_*DH_];
__device__ __half g_Kh[(size_t)B_*H_*T_*DH_];   // compacted
__device__ __half g_Vh[(size_t)B_*H_*T_*DH_];   // compacted
__device__ int g_pos[B_*T_];
__device__ int g_cnt[B_];

// ============================================================================
// mma.sync / ldmatrix / cp.async helpers (base-target PTX)
// ============================================================================
__device__ __forceinline__ unsigned smem_u32(const void* p) {
    unsigned a;
    asm("{ .reg .u64 t; cvta.to.shared.u64 t, %1; cvt.u32.u64 %0, t; }"
        : "=r"(a) : "l"(p));
    return a;
}
__device__ __forceinline__ void mma_fp(float* c, const unsigned* a, const unsigned* b) {
    asm volatile(
        "mma.sync.aligned.m16n8k16.row.col.f32.f16.f16.f32 "
        "{%0,%1,%2,%3}, {%4,%5,%6,%7}, {%8,%9}, {%0,%1,%2,%3};"
        : "+f"(c[0]), "+f"(c[1]), "+f"(c[2]), "+f"(c[3])
        : "r"(a[0]), "r"(a[1]), "r"(a[2]), "r"(a[3]), "r"(b[0]), "r"(b[1]));
}
__device__ __forceinline__ void ldsm4(unsigned* r, unsigned a) {
    asm volatile("ldmatrix.sync.aligned.m8n8.x4.shared.b16 {%0,%1,%2,%3}, [%4];"
        : "=r"(r[0]), "=r"(r[1]), "=r"(r[2]), "=r"(r[3]) : "r"(a));
}
__device__ __forceinline__ void ldsm4t(unsigned* r, unsigned a) {
    asm volatile("ldmatrix.sync.aligned.m8n8.x4.trans.shared.b16 {%0,%1,%2,%3}, [%4];"
        : "=r"(r[0]), "=r"(r[1]), "=r"(r[2]), "=r"(r[3]) : "r"(a));
}
#define CP16(dst_u32, src_ptr) \
    asm volatile("cp.async.cg.shared.global [%0], [%1], 16;" \
        :: "r"(dst_u32), "l"(src_ptr) : "memory")
#define CP_COMMIT() asm volatile("cp.async.commit_group;" ::: "memory")
#define CP_WAIT1()  asm volatile("cp.async.wait_group 1;"  ::: "memory")

// ============================================================================
// scan_mask
// ============================================================================
__global__ void __launch_bounds__(1024) scan_mask(const int* __restrict__ mask)
{
    __shared__ int ps[1024];
    const int b = blockIdx.x, i = threadIdx.x;
    const int a0 = (mask[b*T_ + 2*i]     != 0);
    const int a1 = (mask[b*T_ + 2*i + 1] != 0);
    ps[i] = a0 + a1;
    __syncthreads();
    for (int off = 1; off < 1024; off <<= 1) {
        int v = ps[i] + ((i >= off) ? ps[i - off] : 0);
        __syncthreads();
        ps[i] = v;
        __syncthreads();
    }
    const int excl = (i > 0) ? ps[i-1] : 0;
    g_pos[b*T_ + 2*i]     = a0 ? excl : -1;
    g_pos[b*T_ + 2*i + 1] = a1 ? (excl + a0) : -1;
    if (i == 1023) g_cnt[b] = ps[1023];
}

// ============================================================================
// conversions: fp32 -> fp16 hi only
// ============================================================================
__global__ void __launch_bounds__(256) convA3(
    const float* __restrict__ q, const float* __restrict__ k,
    const float* __restrict__ v, __half* __restrict__ hiB)
{
    const int z = blockIdx.y;
    const float* src = (z == 0) ? q : (z == 1) ? k : v;
    int i = blockIdx.x * 256 + threadIdx.x;
    float4 w = ((const float4*)src)[i];
    __half2 a; a.x = __float2half_rn(w.x); a.y = __float2half_rn(w.y);
    __half2 b; b.x = __float2half_rn(w.z); b.y = __float2half_rn(w.w);
    __half* hi = hiB + z*ASTRIDE;
    ((__half2*)hi)[2*i]   = a;
    ((__half2*)hi)[2*i+1] = b;
}

__global__ void __launch_bounds__(256) convW4(
    const float* __restrict__ wq, const float* __restrict__ wk,
    const float* __restrict__ wv, const float* __restrict__ wo,
    __half* __restrict__ hiB)
{
    const int z = blockIdx.y;
    const float* src = (z == 0) ? wq : (z == 1) ? wk : (z == 2) ? wv : wo;
    int i = blockIdx.x * 256 + threadIdx.x;
    float4 v = ((const float4*)src)[i];
    __half2 ha; ha.x = __float2half_rn(v.x); ha.y = __float2half_rn(v.y);
    __half2 hb; hb.x = __float2half_rn(v.z); hb.y = __float2half_rn(v.w);
    __half* hi = hiB + z*WSTRIDE;
    ((__half2*)hi)[2*i]   = ha;
    ((__half2*)hi)[2*i+1] = hb;
}

// ============================================================================
// GEMM core: Y = Ah @ Wh + bias   (fp16 single-stream)
// cp.async 3-stage pipeline. Stage: Ah 10240B + Wh 8704B = 18944B.
// emode 0: Q proj -> fp16 scatter [B,H,T,64]
// emode 1: K/V proj -> fp16 scatter to COMPACTED rows
// emode 2: dense fp32 out
// ============================================================================
#define GST 18944
#define G_WH_OFF 10240
#define GEMM_SMEM (3*GST)

__device__ __forceinline__ void gemm_core(
    char* gsm,
    const __half* __restrict__ Ah, const __half* __restrict__ Wh,
    const float* __restrict__ bias,
    float* __restrict__ Yf, __half* __restrict__ Yh,
    int emode, int m0, int n0)
{
    const int tid = threadIdx.x, lane = tid & 31, wid = tid >> 5;
    const int wm = wid >> 2, wn = wid & 3;

    float c[4][4][4];
    #pragma unroll
    for (int i = 0; i < 4; i++)
        #pragma unroll
        for (int j = 0; j < 4; j++)
            #pragma unroll
            for (int e = 0; e < 4; e++) c[i][j][e] = 0.f;

    const int l15 = lane & 15, lh8 = (lane >> 4) << 3;
    const unsigned smb = smem_u32(gsm);

    int a_row[2], a_c8[2], w_row[2], w_c8[2];
    #pragma unroll
    for (int t = 0; t < 2; t++) {
        int ch = tid + t*256;
        a_row[t] = ch >> 2;  a_c8[t] = (ch & 3) << 3;
        w_row[t] = ch >> 4;  w_c8[t] = (ch & 15) << 3;
    }

    auto issue = [&](int s, int k0) {
        const unsigned base = smb + s*GST;
        #pragma unroll
        for (int t = 0; t < 2; t++) {
            unsigned aso = base + (unsigned)(a_row[t]*80 + a_c8[t]*2);
            size_t ago = (size_t)(m0 + a_row[t])*1024 + k0 + a_c8[t];
            CP16(aso, Ah + ago);
            unsigned wso = base + G_WH_OFF + (unsigned)(w_row[t]*272 + w_c8[t]*2);
            size_t wgo = (size_t)(k0 + w_row[t])*1024 + n0 + w_c8[t];
            CP16(wso, Wh + wgo);
        }
    };

    issue(0, 0);
    CP_COMMIT();
    issue(1, 32);
    CP_COMMIT();

    for (int kc = 0; kc < 32; kc++) {
        CP_WAIT1();
        __syncthreads();
        if (kc + 2 < 32) issue((kc + 2) % 3, (kc + 2) << 5);
        CP_COMMIT();

        const int buf = kc % 3;
        const __half* sAh = (const __half*)(gsm + buf*GST);
        const __half* sWh = (const __half*)(gsm + buf*GST + G_WH_OFF);

        #pragma unroll
        for (int kk = 0; kk < 32; kk += 16) {
            unsigned a[4][4], bh_[4][2], t4[4];
            #pragma unroll
            for (int mi = 0; mi < 4; mi++)
                ldsm4(a[mi], smem_u32(&sAh[(wm*64 + mi*16 + l15)*40 + kk + lh8]));
            #pragma unroll
            for (int p = 0; p < 2; p++) {
                ldsm4t(t4, smem_u32(&sWh[(kk + l15)*136 + wn*32 + p*16 + lh8]));
                bh_[2*p][0]=t4[0]; bh_[2*p][1]=t4[1];
                bh_[2*p+1][0]=t4[2]; bh_[2*p+1][1]=t4[3];
            }
            #pragma unroll
            for (int mi = 0; mi < 4; mi++)
                #pragma unroll
                for (int ni = 0; ni < 4; ni++) mma_fp(c[mi][ni], a[mi], bh_[ni]);
        }
    }

    // Epilogue
    const int rA = lane >> 2, c2 = (lane & 3) << 1;
    #pragma unroll
    for (int mi = 0; mi < 4; mi++) {
        const int rowA = m0 + wm*64 + mi*16 + rA;
        const int rowB = rowA + 8;
        int pA = rowA & (T_-1), pB = rowB & (T_-1);
        if (emode == 1) { pA = g_pos[rowA]; pB = g_pos[rowB]; }
        #pragma unroll
        for (int ni = 0; ni < 4; ni++) {
            const int col = n0 + wn*32 + ni*8 + c2;
            float2 bb = *(const float2*)(bias + col);
            float v00 = c[mi][ni][0] + bb.x, v01 = c[mi][ni][1] + bb.y;
            float v10 = c[mi][ni][2] + bb.x, v11 = c[mi][ni][3] + bb.y;
            if (emode == 2) {
                float2 w0; w0.x = v00; w0.y = v01;
                float2 w1; w1.x = v10; w1.y = v11;
                *(float2*)(Yf + (size_t)rowA * 1024 + col) = w0;
                *(float2*)(Yf + (size_t)rowB * 1024 + col) = w1;
            } else {
                const int hh = col >> 6, dd = col & 63;
                const int bA = rowA >> 11, bB = rowB >> 11;
                __half2 ph0; ph0.x = __float2half_rn(v00); ph0.y = __float2half_rn(v01);
                __half2 ph1; ph1.x = __float2half_rn(v10); ph1.y = __float2half_rn(v11);
                if (pA >= 0) {
                    size_t oA = (((size_t)(bA*H_ + hh))*T_ + pA)*64 + dd;
                    *(__half2*)(Yh + oA) = ph0;
                }
                if (pB >= 0) {
                    size_t oB = (((size_t)(bB*H_ + hh))*T_ + pB)*64 + dd;
                    *(__half2*)(Yh + oB) = ph1;
                }
            }
        }
    }
}

__global__ void __launch_bounds__(256, 2) gemm_qkv(
    const __half* __restrict__ AhB, const __half* __restrict__ WhB,
    const float* __restrict__ bq, const float* __restrict__ bk,
    const float* __restrict__ bv,
    __half* __restrict__ Qh, __half* __restrict__ Kh, __half* __restrict__ Vh)
{
    extern __shared__ __align__(16) char gsm[];
    const int z = blockIdx.z;
    const float* bias = (z == 0) ? bq : (z == 1) ? bk : bv;
    __half* Yh = (z == 0) ? Qh : (z == 1) ? Kh : Vh;
    gemm_core(gsm, AhB + z*ASTRIDE, WhB + z*WSTRIDE, bias,
              nullptr, Yh, (z == 0) ? 0 : 1,
              blockIdx.y << 7, blockIdx.x << 7);
}

__global__ void __launch_bounds__(256, 2) gemm_out(
    const __half* __restrict__ AhB, const __half* __restrict__ WhB,
    const float* __restrict__ bo, float* __restrict__ out)
{
    extern __shared__ __align__(16) char gsm[];
    gemm_core(gsm, AhB, WhB + 3*WSTRIDE, bo,
              out, nullptr, 2, blockIdx.y << 7, blockIdx.x << 7);
}

// ============================================================================
// Flash attention (fp16, all single-stream): S = Qh·Kh; PV = Ph·Vh.
// Compacted keys, cp.async 2-buf, 2 CTA/SM. Writes fp16 ctx into g_Ah slab 0.
// ============================================================================
#define ATT_QH   0          /* 128 x 72 half = 18432 */
#define ATT_K    18432      /* 2 bufs x Kh 9216 = 18432 */
#define ATT_V    36864      /* 2 bufs x Vh 9216 = 18432 */
#define ATT_PH   55296      /* 128 x 72 half = 18432 */
#define ATT_PSUM 73728      /* 512 floats */
#define ATT_LS   75776      /* 128 floats */
#define ATT_SMEM 76288

__global__ void __launch_bounds__(256, 2) attn_mma()
{
    extern __shared__ __align__(16) char sm[];
    __half* sQh = (__half*)(sm + ATT_QH);
    __half* sPh = (__half*)(sm + ATT_PH);
    float* psum = (float*)(sm + ATT_PSUM);
    float* l_s  = (float*)(sm + ATT_LS);

    const int tid = threadIdx.x, lane = tid & 31, wid = tid >> 5;
    const int wm = wid >> 2, wn = wid & 3;
    const int qt0 = blockIdx.x << 7;
    const int hh = blockIdx.y, bb = blockIdx.z;
    const size_t base = ((size_t)(bb*H_ + hh)) * T_ * DH_;
    const int nv = g_cnt[bb];
    const int nt = (nv + 63) >> 6;

    const int r = tid >> 1, cofs = (tid & 1) << 5;
    const int l15 = lane & 15, lh8 = (lane >> 4) << 3;
    const int bn  = (lane & 7) + ((lane >> 4) << 3), bk8 = ((lane >> 3) & 1) << 3;
    const int rA0 = lane >> 2, c2 = (lane & 3) << 1;

    const unsigned smK = smem_u32(sm + ATT_K);
    const unsigned smV = smem_u32(sm + ATT_V);

    int ld_row[2], ld_c8[2];
    #pragma unroll
    for (int t = 0; t < 2; t++) {
        int ch = tid + t*256;
        ld_row[t] = ch >> 3;
        ld_c8[t]  = (ch & 7) << 3;
    }

    // Load Q hi (persistent)
    {
        const uint4* s1 = (const uint4*)(g_Qh + base + (size_t)(qt0 + r)*64 + cofs);
        uint4* d1 = (uint4*)(sQh + r*72 + cofs);
        d1[0]=s1[0]; d1[1]=s1[1]; d1[2]=s1[2]; d1[3]=s1[3];
    }
    if (tid < 128) l_s[tid] = 0.f;

    float o[4][2][4];
    #pragma unroll
    for (int i = 0; i < 4; i++)
        #pragma unroll
        for (int j = 0; j < 2; j++)
            #pragma unroll
            for (int e = 0; e < 4; e++) o[i][j][e] = 0.f;

    // Prologue: tile 0 -> buf 0
    #pragma unroll
    for (int t = 0; t < 2; t++) {
        unsigned so = (unsigned)((ld_row[t]*72 + ld_c8[t]) * 2);
        size_t go = base + (size_t)ld_row[t]*64 + ld_c8[t];
        CP16(smK + so, g_Kh + go);
        CP16(smV + so, g_Vh + go);
    }
    CP_COMMIT();

    for (int kt = 0; kt < nt; kt++) {
        const int buf = kt & 1;
        if (kt + 1 < nt) {
            const size_t gofs = base + ((size_t)(kt+1) << 6) * 64;
            const unsigned kb = smK + (buf ^ 1) * 9216u;
            const unsigned vb = smV + (buf ^ 1) * 9216u;
            #pragma unroll
            for (int t = 0; t < 2; t++) {
                unsigned so = (unsigned)((ld_row[t]*72 + ld_c8[t]) * 2);
                size_t go = gofs + (size_t)ld_row[t]*64 + ld_c8[t];
                CP16(kb + so, g_Kh + go);
                CP16(vb + so, g_Vh + go);
            }
        }
        CP_COMMIT();
        CP_WAIT1();
        __syncthreads();   // (A)

        __half* sKh = (__half*)(sm + ATT_K + buf*9216);
        __half* sVh = (__half*)(sm + ATT_V + buf*9216);

        // ---- S = Qh·Kh ----
        float s[4][2][4];
        #pragma unroll
        for (int i = 0; i < 4; i++)
            #pragma unroll
            for (int j = 0; j < 2; j++)
                #pragma unroll
                for (int e = 0; e < 4; e++) s[i][j][e] = 0.f;

        #pragma unroll
        for (int kk = 0; kk < 64; kk += 16) {
            unsigned a[4][4], bhf[2][2], t4[4];
            #pragma unroll
            for (int mi = 0; mi < 4; mi++)
                ldsm4(a[mi], smem_u32(&sQh[(wm*64 + mi*16 + l15)*72 + kk + lh8]));
            ldsm4(t4, smem_u32(&sKh[(wn*16 + bn)*72 + kk + bk8]));
            bhf[0][0]=t4[0]; bhf[0][1]=t4[1]; bhf[1][0]=t4[2]; bhf[1][1]=t4[3];
            #pragma unroll
            for (int mi = 0; mi < 4; mi++)
                #pragma unroll
                for (int ni = 0; ni < 2; ni++) mma_fp(s[mi][ni], a[mi], bhf[ni]);
        }

        // ---- p = (col valid) ? exp(s*scale) : 0; row sums; write Ph ----
        const int k0g = kt << 6;
        #pragma unroll
        for (int mi = 0; mi < 4; mi++) {
            float sumA = 0.f, sumB = 0.f;
            const int rowA = wm*64 + mi*16 + rA0;
            #pragma unroll
            for (int ni = 0; ni < 2; ni++) {
                const int col = wn*16 + ni*8 + c2;
                const bool v0 = (k0g + col)     < nv;
                const bool v1 = (k0g + col + 1) < nv;
                float p00 = v0 ? __expf(s[mi][ni][0]*SCALE_) : 0.f;
                float p01 = v1 ? __expf(s[mi][ni][1]*SCALE_) : 0.f;
                float p10 = v0 ? __expf(s[mi][ni][2]*SCALE_) : 0.f;
                float p11 = v1 ? __expf(s[mi][ni][3]*SCALE_) : 0.f;
                sumA += p00 + p01;  sumB += p10 + p11;
                __half2 vh0; vh0.x = __float2half_rn(p00); vh0.y = __float2half_rn(p01);
                __half2 vh1; vh1.x = __float2half_rn(p10); vh1.y = __float2half_rn(p11);
                *(__half2*)(sPh + rowA*72 + col)      = vh0;
                *(__half2*)(sPh + (rowA+8)*72 + col)  = vh1;
            }
            sumA += __shfl_xor_sync(0xffffffffu, sumA, 1);
            sumA += __shfl_xor_sync(0xffffffffu, sumA, 2);
            sumB += __shfl_xor_sync(0xffffffffu, sumB, 1);
            sumB += __shfl_xor_sync(0xffffffffu, sumB, 2);
            if ((lane & 3) == 0) {
                psum[rowA*4 + wn]     = sumA;
                psum[(rowA+8)*4 + wn] = sumB;
            }
        }
        __syncthreads();   // (B)

        if (tid < 128)
            l_s[tid] += psum[tid*4+0] + psum[tid*4+1] + psum[tid*4+2] + psum[tid*4+3];

        // ---- O += Ph·Vh ----
        #pragma unroll
        for (int kk = 0; kk < 64; kk += 16) {
            unsigned pa[4][4], vhf[2][2], t4[4];
            #pragma unroll
            for (int mi = 0; mi < 4; mi++)
                ldsm4(pa[mi], smem_u32(&sPh[(wm*64 + mi*16 + l15)*72 + kk + lh8]));
            ldsm4t(t4, smem_u32(&sVh[(kk + l15)*72 + wn*16 + lh8]));
            vhf[0][0]=t4[0]; vhf[0][1]=t4[1]; vhf[1][0]=t4[2]; vhf[1][1]=t4[3];
            #pragma unroll
            for (int mi = 0; mi < 4; mi++)
                #pragma unroll
                for (int ni = 0; ni < 2; ni++) mma_fp(o[mi][ni], pa[mi], vhf[ni]);
        }
        __syncthreads();   // (C)
    }

    // ---- normalize + write fp16 ctx into g_Ah slab 0 ----
    #pragma unroll
    for (int mi = 0; mi < 4; mi++) {
        const int rowA = wm*64 + mi*16 + rA0, rowB = rowA + 8;
        const float invA = 1.f / l_s[rowA], invB = 1.f / l_s[rowB];
        #pragma unroll
        for (int ni = 0; ni < 2; ni++) {
            const int col = wn*16 + ni*8 + c2;
            __half2 w0; w0.x = __float2half_rn(o[mi][ni][0]*invA);
            w0.y = __float2half_rn(o[mi][ni][1]*invA);
            __half2 w1; w1.x = __float2half_rn(o[mi][ni][2]*invB);
            w1.y = __float2half_rn(o[mi][ni][3]*invB);
            *(__half2*)(g_Ah + (size_t)(bb*T_ + qt0 + rowA)*D_ + hh*64 + col) = w0;
            *(__half2*)(g_Ah + (size_t)(bb*T_ + qt0 + rowB)*D_ + hh*64 + col) = w1;
        }
    }
}

// ============================================================================
extern "C" void kernel_launch(void* const* d_in, const int* in_sizes, int n_in,
                              void* d_out, int out_size)
{
    const float* q  = (const float*)d_in[0];
    const float* k  = (const float*)d_in[1];
    const float* v  = (const float*)d_in[2];
    const int*  mk  = (const int*)  d_in[3];
    const float* Wq = (const float*)d_in[4];
    const float* bq = (const float*)d_in[5];
    const float* Wk = (const float*)d_in[6];
    const float* bk = (const float*)d_in[7];
    const float* Wv = (const float*)d_in[8];
    const float* bv = (const float*)d_in[9];
    const float* Wo = (const float*)d_in[10];
    const float* bo = (const float*)d_in[11];
    float* out = (float*)d_out;

    __half *pAh, *pWh, *pQh, *pKh, *pVh;
    cudaGetSymbolAddress((void**)&pAh, g_Ah);
    cudaGetSymbolAddress((void**)&pWh, g_Wh);
    cudaGetSymbolAddress((void**)&pQh, g_Qh);
    cudaGetSymbolAddress((void**)&pKh, g_Kh);
    cudaGetSymbolAddress((void**)&pVh, g_Vh);

    cudaFuncSetAttribute(gemm_qkv,
                         cudaFuncAttributeMaxDynamicSharedMemorySize, GEMM_SMEM);
    cudaFuncSetAttribute(gemm_out,
                         cudaFuncAttributeMaxDynamicSharedMemorySize, GEMM_SMEM);
    cudaFuncSetAttribute(attn_mma,
                         cudaFuncAttributeMaxDynamicSharedMemorySize, ATT_SMEM);

    dim3 blk(256);

    scan_mask<<<B_, 1024>>>(mk);
    convW4<<<dim3(1024, 4), blk>>>(Wq, Wk, Wv, Wo, pWh);
    convA3<<<dim3(4096, 3), blk>>>(q, k, v, pAh);
    gemm_qkv<<<dim3(8, 32, 3), blk, GEMM_SMEM>>>(
        pAh, pWh, bq, bk, bv, pQh, pKh, pVh);
    attn_mma<<<dim3(16, 16, 2), blk, ATT_SMEM>>>();   // writes fp16 ctx -> g_Ah
    gemm_out<<<dim3(8, 32), blk, GEMM_SMEM>>>(pAh, pWh, bo, out);
}

// round 13
// speedup vs baseline: 2.4639x; 1.1142x over previous
#include <cuda_runtime.h>
#include <cuda_fp16.h>
#include <math.h>
#include <stdint.h>

#define B_ 2
#define T_ 2048
#define D_ 1024
#define H_ 16
#define DH_ 64
#define SCALE_ 0.03125f     /* 1/sqrt(1024) exactly */

#define ASTRIDE ((size_t)4096*1024)
#define WSTRIDE ((size_t)1024*1024)

// ============================================================================
// Scratch (static device globals — no allocation in kernel_launch)
// g_Ah slab 0 doubles as the fp16 context buffer (attention epilogue output).
// ============================================================================
__device__ __half g_Ah[3*ASTRIDE];
__device__ __half g_Wh[4*WSTRIDE];
__device__ __half g_Qh[(size_t)B_*H_*T_*DH_];
__device__ __half g_Kh[(size_t)B_*H_*T_*DH_];   // compacted
__device__ __half g_Vh[(size_t)B_*H_*T_*DH_];   // compacted
__device__ int g_pos[B_*T_];
__device__ int g_cnt[B_];

// ============================================================================
// mma.sync / ldmatrix / cp.async helpers (base-target PTX)
// ============================================================================
__device__ __forceinline__ unsigned smem_u32(const void* p) {
    unsigned a;
    asm("{ .reg .u64 t; cvta.to.shared.u64 t, %1; cvt.u32.u64 %0, t; }"
        : "=r"(a) : "l"(p));
    return a;
}
__device__ __forceinline__ void mma_fp(float* c, const unsigned* a, const unsigned* b) {
    asm volatile(
        "mma.sync.aligned.m16n8k16.row.col.f32.f16.f16.f32 "
        "{%0,%1,%2,%3}, {%4,%5,%6,%7}, {%8,%9}, {%0,%1,%2,%3};"
        : "+f"(c[0]), "+f"(c[1]), "+f"(c[2]), "+f"(c[3])
        : "r"(a[0]), "r"(a[1]), "r"(a[2]), "r"(a[3]), "r"(b[0]), "r"(b[1]));
}
__device__ __forceinline__ void ldsm4(unsigned* r, unsigned a) {
    asm volatile("ldmatrix.sync.aligned.m8n8.x4.shared.b16 {%0,%1,%2,%3}, [%4];"
        : "=r"(r[0]), "=r"(r[1]), "=r"(r[2]), "=r"(r[3]) : "r"(a));
}
__device__ __forceinline__ void ldsm4t(unsigned* r, unsigned a) {
    asm volatile("ldmatrix.sync.aligned.m8n8.x4.trans.shared.b16 {%0,%1,%2,%3}, [%4];"
        : "=r"(r[0]), "=r"(r[1]), "=r"(r[2]), "=r"(r[3]) : "r"(a));
}
#define CP16(dst_u32, src_ptr) \
    asm volatile("cp.async.cg.shared.global [%0], [%1], 16;" \
        :: "r"(dst_u32), "l"(src_ptr) : "memory")
#define CP_COMMIT() asm volatile("cp.async.commit_group;" ::: "memory")
#define CP_WAIT1()  asm volatile("cp.async.wait_group 1;"  ::: "memory")

// ============================================================================
// prep: fused convA (q,k,v -> fp16), convW (4 weights -> fp16), mask scan.
// grid.x = 16386 blocks of 256 threads:
//   [0, 12288)      convA  (z = bid/4096)
//   [12288, 16384)  convW  (z = (bid-12288)/1024)
//   [16384, 16386)  per-batch mask prefix scan (256 thr x 8 elems)
// ============================================================================
__global__ void __launch_bounds__(256) prep(
    const float* __restrict__ q, const float* __restrict__ k,
    const float* __restrict__ v,
    const float* __restrict__ wq, const float* __restrict__ wk,
    const float* __restrict__ wv, const float* __restrict__ wo,
    const int* __restrict__ mask,
    __half* __restrict__ AhB, __half* __restrict__ WhB)
{
    const int bid = blockIdx.x, tid = threadIdx.x;
    if (bid < 12288) {
        const int z = bid >> 12;
        const float* src = (z == 0) ? q : (z == 1) ? k : v;
        int i = (bid & 4095) * 256 + tid;
        float4 w = ((const float4*)src)[i];
        __half2 a; a.x = __float2half_rn(w.x); a.y = __float2half_rn(w.y);
        __half2 b; b.x = __float2half_rn(w.z); b.y = __float2half_rn(w.w);
        __half* hi = AhB + (size_t)z*ASTRIDE;
        ((__half2*)hi)[2*i]   = a;
        ((__half2*)hi)[2*i+1] = b;
    } else if (bid < 16384) {
        const int zb = bid - 12288;
        const int z = zb >> 10;
        const float* src = (z == 0) ? wq : (z == 1) ? wk : (z == 2) ? wv : wo;
        int i = (zb & 1023) * 256 + tid;
        float4 w = ((const float4*)src)[i];
        __half2 a; a.x = __float2half_rn(w.x); a.y = __float2half_rn(w.y);
        __half2 b; b.x = __float2half_rn(w.z); b.y = __float2half_rn(w.w);
        __half* hi = WhB + (size_t)z*WSTRIDE;
        ((__half2*)hi)[2*i]   = a;
        ((__half2*)hi)[2*i+1] = b;
    } else {
        __shared__ int ps[256];
        const int b = bid - 16384;
        const int base = b*T_ + tid*8;
        int a[8], s = 0;
        #pragma unroll
        for (int j = 0; j < 8; j++) { a[j] = (mask[base + j] != 0); s += a[j]; }
        ps[tid] = s;
        __syncthreads();
        for (int off = 1; off < 256; off <<= 1) {
            int vsum = ps[tid] + ((tid >= off) ? ps[tid - off] : 0);
            __syncthreads();
            ps[tid] = vsum;
            __syncthreads();
        }
        int run = (tid > 0) ? ps[tid-1] : 0;
        #pragma unroll
        for (int j = 0; j < 8; j++) {
            g_pos[base + j] = a[j] ? run : -1;
            run += a[j];
        }
        if (tid == 255) g_cnt[b] = ps[255];
    }
}

// ============================================================================
// GEMM core: Y = Ah @ Wh + bias   (fp16 single-stream) — unchanged from R11
// ============================================================================
#define GST 18944
#define G_WH_OFF 10240
#define GEMM_SMEM (3*GST)

__device__ __forceinline__ void gemm_core(
    char* gsm,
    const __half* __restrict__ Ah, const __half* __restrict__ Wh,
    const float* __restrict__ bias,
    float* __restrict__ Yf, __half* __restrict__ Yh,
    int emode, int m0, int n0)
{
    const int tid = threadIdx.x, lane = tid & 31, wid = tid >> 5;
    const int wm = wid >> 2, wn = wid & 3;

    float c[4][4][4];
    #pragma unroll
    for (int i = 0; i < 4; i++)
        #pragma unroll
        for (int j = 0; j < 4; j++)
            #pragma unroll
            for (int e = 0; e < 4; e++) c[i][j][e] = 0.f;

    const int l15 = lane & 15, lh8 = (lane >> 4) << 3;
    const unsigned smb = smem_u32(gsm);

    int a_row[2], a_c8[2], w_row[2], w_c8[2];
    #pragma unroll
    for (int t = 0; t < 2; t++) {
        int ch = tid + t*256;
        a_row[t] = ch >> 2;  a_c8[t] = (ch & 3) << 3;
        w_row[t] = ch >> 4;  w_c8[t] = (ch & 15) << 3;
    }

    auto issue = [&](int s, int k0) {
        const unsigned base = smb + s*GST;
        #pragma unroll
        for (int t = 0; t < 2; t++) {
            unsigned aso = base + (unsigned)(a_row[t]*80 + a_c8[t]*2);
            size_t ago = (size_t)(m0 + a_row[t])*1024 + k0 + a_c8[t];
            CP16(aso, Ah + ago);
            unsigned wso = base + G_WH_OFF + (unsigned)(w_row[t]*272 + w_c8[t]*2);
            size_t wgo = (size_t)(k0 + w_row[t])*1024 + n0 + w_c8[t];
            CP16(wso, Wh + wgo);
        }
    };

    issue(0, 0);
    CP_COMMIT();
    issue(1, 32);
    CP_COMMIT();

    for (int kc = 0; kc < 32; kc++) {
        CP_WAIT1();
        __syncthreads();
        if (kc + 2 < 32) issue((kc + 2) % 3, (kc + 2) << 5);
        CP_COMMIT();

        const int buf = kc % 3;
        const __half* sAh = (const __half*)(gsm + buf*GST);
        const __half* sWh = (const __half*)(gsm + buf*GST + G_WH_OFF);

        #pragma unroll
        for (int kk = 0; kk < 32; kk += 16) {
            unsigned a[4][4], bh_[4][2], t4[4];
            #pragma unroll
            for (int mi = 0; mi < 4; mi++)
                ldsm4(a[mi], smem_u32(&sAh[(wm*64 + mi*16 + l15)*40 + kk + lh8]));
            #pragma unroll
            for (int p = 0; p < 2; p++) {
                ldsm4t(t4, smem_u32(&sWh[(kk + l15)*136 + wn*32 + p*16 + lh8]));
                bh_[2*p][0]=t4[0]; bh_[2*p][1]=t4[1];
                bh_[2*p+1][0]=t4[2]; bh_[2*p+1][1]=t4[3];
            }
            #pragma unroll
            for (int mi = 0; mi < 4; mi++)
                #pragma unroll
                for (int ni = 0; ni < 4; ni++) mma_fp(c[mi][ni], a[mi], bh_[ni]);
        }
    }

    // Epilogue
    const int rA = lane >> 2, c2 = (lane & 3) << 1;
    #pragma unroll
    for (int mi = 0; mi < 4; mi++) {
        const int rowA = m0 + wm*64 + mi*16 + rA;
        const int rowB = rowA + 8;
        int pA = rowA & (T_-1), pB = rowB & (T_-1);
        if (emode == 1) { pA = g_pos[rowA]; pB = g_pos[rowB]; }
        #pragma unroll
        for (int ni = 0; ni < 4; ni++) {
            const int col = n0 + wn*32 + ni*8 + c2;
            float2 bb = *(const float2*)(bias + col);
            float v00 = c[mi][ni][0] + bb.x, v01 = c[mi][ni][1] + bb.y;
            float v10 = c[mi][ni][2] + bb.x, v11 = c[mi][ni][3] + bb.y;
            if (emode == 2) {
                float2 w0; w0.x = v00; w0.y = v01;
                float2 w1; w1.x = v10; w1.y = v11;
                *(float2*)(Yf + (size_t)rowA * 1024 + col) = w0;
                *(float2*)(Yf + (size_t)rowB * 1024 + col) = w1;
            } else {
                const int hh = col >> 6, dd = col & 63;
                const int bA = rowA >> 11, bB = rowB >> 11;
                __half2 ph0; ph0.x = __float2half_rn(v00); ph0.y = __float2half_rn(v01);
                __half2 ph1; ph1.x = __float2half_rn(v10); ph1.y = __float2half_rn(v11);
                if (pA >= 0) {
                    size_t oA = (((size_t)(bA*H_ + hh))*T_ + pA)*64 + dd;
                    *(__half2*)(Yh + oA) = ph0;
                }
                if (pB >= 0) {
                    size_t oB = (((size_t)(bB*H_ + hh))*T_ + pB)*64 + dd;
                    *(__half2*)(Yh + oB) = ph1;
                }
            }
        }
    }
}

__global__ void __launch_bounds__(256, 2) gemm_qkv(
    const __half* __restrict__ AhB, const __half* __restrict__ WhB,
    const float* __restrict__ bq, const float* __restrict__ bk,
    const float* __restrict__ bv,
    __half* __restrict__ Qh, __half* __restrict__ Kh, __half* __restrict__ Vh)
{
    extern __shared__ __align__(16) char gsm[];
    const int z = blockIdx.z;
    const float* bias = (z == 0) ? bq : (z == 1) ? bk : bv;
    __half* Yh = (z == 0) ? Qh : (z == 1) ? Kh : Vh;
    gemm_core(gsm, AhB + z*ASTRIDE, WhB + z*WSTRIDE, bias,
              nullptr, Yh, (z == 0) ? 0 : 1,
              blockIdx.y << 7, blockIdx.x << 7);
}

__global__ void __launch_bounds__(256, 2) gemm_out(
    const __half* __restrict__ AhB, const __half* __restrict__ WhB,
    const float* __restrict__ bo, float* __restrict__ out)
{
    extern __shared__ __align__(16) char gsm[];
    gemm_core(gsm, AhB, WhB + 3*WSTRIDE, bo,
              out, nullptr, 2, blockIdx.y << 7, blockIdx.x << 7);
}

// ============================================================================
// Flash attention, warp-per-row-group layout:
// 8 warps each own 16 q-rows and ALL 64 keys / 64 dh of the tile.
// Softmax fully warp-local (register row sums, warp-private P, no psum/l_s).
// S = Qh·Kh; PV = Ph·Vh. Compacted keys, cp.async double-buffer, 2 CTA/SM.
// ============================================================================
#define ATT_QH   0          /* 128 x 72 half = 18432 */
#define ATT_K    18432      /* 2 bufs x 9216 */
#define ATT_V    36864      /* 2 bufs x 9216 */
#define ATT_PH   55296      /* 128 x 72 half = 18432 */
#define ATT_SMEM 73728

__global__ void __launch_bounds__(256, 2) attn_mma()
{
    extern __shared__ __align__(16) char sm[];
    __half* sQh = (__half*)(sm + ATT_QH);
    __half* sPh = (__half*)(sm + ATT_PH);

    const int tid = threadIdx.x, lane = tid & 31, wid = tid >> 5;
    const int qt0 = blockIdx.x << 7;
    const int hh = blockIdx.y, bb = blockIdx.z;
    const size_t base = ((size_t)(bb*H_ + hh)) * T_ * DH_;
    const int nv = g_cnt[bb];
    const int nt = (nv + 63) >> 6;

    const int r = tid >> 1, cofs = (tid & 1) << 5;
    const int l15 = lane & 15, lh8 = (lane >> 4) << 3;
    const int bn  = (lane & 7) + ((lane >> 4) << 3), bk8 = ((lane >> 3) & 1) << 3;
    const int rA0 = lane >> 2, c2 = (lane & 3) << 1;

    const unsigned smK = smem_u32(sm + ATT_K);
    const unsigned smV = smem_u32(sm + ATT_V);

    int ld_row[2], ld_c8[2];
    #pragma unroll
    for (int t = 0; t < 2; t++) {
        int ch = tid + t*256;
        ld_row[t] = ch >> 3;
        ld_c8[t]  = (ch & 7) << 3;
    }

    // Load Q (persistent)
    {
        const uint4* s1 = (const uint4*)(g_Qh + base + (size_t)(qt0 + r)*64 + cofs);
        uint4* d1 = (uint4*)(sQh + r*72 + cofs);
        d1[0]=s1[0]; d1[1]=s1[1]; d1[2]=s1[2]; d1[3]=s1[3];
    }

    float lrunA = 0.f, lrunB = 0.f;
    float o[8][4];
    #pragma unroll
    for (int g = 0; g < 8; g++)
        #pragma unroll
        for (int e = 0; e < 4; e++) o[g][e] = 0.f;

    // Prologue: tile 0 -> buf 0
    #pragma unroll
    for (int t = 0; t < 2; t++) {
        unsigned so = (unsigned)((ld_row[t]*72 + ld_c8[t]) * 2);
        size_t go = base + (size_t)ld_row[t]*64 + ld_c8[t];
        CP16(smK + so, g_Kh + go);
        CP16(smV + so, g_Vh + go);
    }
    CP_COMMIT();

    const int prow = wid*16;   // this warp's q-row block

    for (int kt = 0; kt < nt; kt++) {
        const int buf = kt & 1;
        if (kt + 1 < nt) {
            const size_t gofs = base + ((size_t)(kt+1) << 6) * 64;
            const unsigned kb = smK + (buf ^ 1) * 9216u;
            const unsigned vb = smV + (buf ^ 1) * 9216u;
            #pragma unroll
            for (int t = 0; t < 2; t++) {
                unsigned so = (unsigned)((ld_row[t]*72 + ld_c8[t]) * 2);
                size_t go = gofs + (size_t)ld_row[t]*64 + ld_c8[t];
                CP16(kb + so, g_Kh + go);
                CP16(vb + so, g_Vh + go);
            }
        }
        CP_COMMIT();
        CP_WAIT1();
        __syncthreads();   // (A) current K/V buffer ready

        __half* sKh = (__half*)(sm + ATT_K + buf*9216);
        __half* sVh = (__half*)(sm + ATT_V + buf*9216);

        // ---- S = Qh·Kh : warp computes 16 rows x 64 keys ----
        float s[8][4];
        #pragma unroll
        for (int g = 0; g < 8; g++)
            #pragma unroll
            for (int e = 0; e < 4; e++) s[g][e] = 0.f;

        #pragma unroll
        for (int kk = 0; kk < 64; kk += 16) {
            unsigned a[4], bf[8][2], t4[4];
            ldsm4(a, smem_u32(&sQh[(prow + l15)*72 + kk + lh8]));
            #pragma unroll
            for (int g = 0; g < 4; g++) {
                ldsm4(t4, smem_u32(&sKh[(g*16 + bn)*72 + kk + bk8]));
                bf[2*g][0]=t4[0]; bf[2*g][1]=t4[1];
                bf[2*g+1][0]=t4[2]; bf[2*g+1][1]=t4[3];
            }
            #pragma unroll
            for (int G = 0; G < 8; G++) mma_fp(s[G], a, bf[G]);
        }

        // ---- warp-local softmax: p = valid ? exp(s*scale) : 0 ----
        const int k0g = kt << 6;
        float sumA = 0.f, sumB = 0.f;
        #pragma unroll
        for (int G = 0; G < 8; G++) {
            const int col = G*8 + c2;
            const bool v0 = (k0g + col)     < nv;
            const bool v1 = (k0g + col + 1) < nv;
            float p00 = v0 ? __expf(s[G][0]*SCALE_) : 0.f;
            float p01 = v1 ? __expf(s[G][1]*SCALE_) : 0.f;
            float p10 = v0 ? __expf(s[G][2]*SCALE_) : 0.f;
            float p11 = v1 ? __expf(s[G][3]*SCALE_) : 0.f;
            sumA += p00 + p01;  sumB += p10 + p11;
            __half2 vh0; vh0.x = __float2half_rn(p00); vh0.y = __float2half_rn(p01);
            __half2 vh1; vh1.x = __float2half_rn(p10); vh1.y = __float2half_rn(p11);
            *(__half2*)(sPh + (prow + rA0)*72 + col)     = vh0;
            *(__half2*)(sPh + (prow + rA0 + 8)*72 + col) = vh1;
        }
        sumA += __shfl_xor_sync(0xffffffffu, sumA, 1);
        sumA += __shfl_xor_sync(0xffffffffu, sumA, 2);
        sumB += __shfl_xor_sync(0xffffffffu, sumB, 1);
        sumB += __shfl_xor_sync(0xffffffffu, sumB, 2);
        lrunA += sumA;
        lrunB += sumB;
        __syncwarp();   // P visible across lanes for ldmatrix

        // ---- O += Ph·Vh : warp computes 16 rows x 64 dh ----
        #pragma unroll
        for (int kk = 0; kk < 64; kk += 16) {
            unsigned pa[4], vf[8][2], t4[4];
            ldsm4(pa, smem_u32(&sPh[(prow + l15)*72 + kk + lh8]));
            #pragma unroll
            for (int g = 0; g < 4; g++) {
                ldsm4t(t4, smem_u32(&sVh[(kk + l15)*72 + g*16 + lh8]));
                vf[2*g][0]=t4[0]; vf[2*g][1]=t4[1];
                vf[2*g+1][0]=t4[2]; vf[2*g+1][1]=t4[3];
            }
            #pragma unroll
            for (int G = 0; G < 8; G++) mma_fp(o[G], pa, vf[G]);
        }
        __syncthreads();   // (C) all warps done with buf before it is refilled
    }

    // ---- normalize + write fp16 ctx into g_Ah slab 0 ----
    const float invA = 1.f / lrunA, invB = 1.f / lrunB;
    const size_t rowA = (size_t)(bb*T_ + qt0 + prow + rA0) * D_ + hh*64;
    const size_t rowB = rowA + (size_t)8 * D_;
    #pragma unroll
    for (int G = 0; G < 8; G++) {
        const int col = G*8 + c2;
        __half2 w0; w0.x = __float2half_rn(o[G][0]*invA);
        w0.y = __float2half_rn(o[G][1]*invA);
        __half2 w1; w1.x = __float2half_rn(o[G][2]*invB);
        w1.y = __float2half_rn(o[G][3]*invB);
        *(__half2*)(g_Ah + rowA + col) = w0;
        *(__half2*)(g_Ah + rowB + col) = w1;
    }
}

// ============================================================================
extern "C" void kernel_launch(void* const* d_in, const int* in_sizes, int n_in,
                              void* d_out, int out_size)
{
    const float* q  = (const float*)d_in[0];
    const float* k  = (const float*)d_in[1];
    const float* v  = (const float*)d_in[2];
    const int*  mk  = (const int*)  d_in[3];
    const float* Wq = (const float*)d_in[4];
    const float* bq = (const float*)d_in[5];
    const float* Wk = (const float*)d_in[6];
    const float* bk = (const float*)d_in[7];
    const float* Wv = (const float*)d_in[8];
    const float* bv = (const float*)d_in[9];
    const float* Wo = (const float*)d_in[10];
    const float* bo = (const float*)d_in[11];
    float* out = (float*)d_out;

    __half *pAh, *pWh, *pQh, *pKh, *pVh;
    cudaGetSymbolAddress((void**)&pAh, g_Ah);
    cudaGetSymbolAddress((void**)&pWh, g_Wh);
    cudaGetSymbolAddress((void**)&pQh, g_Qh);
    cudaGetSymbolAddress((void**)&pKh, g_Kh);
    cudaGetSymbolAddress((void**)&pVh, g_Vh);

    cudaFuncSetAttribute(gemm_qkv,
                         cudaFuncAttributeMaxDynamicSharedMemorySize, GEMM_SMEM);
    cudaFuncSetAttribute(gemm_out,
                         cudaFuncAttributeMaxDynamicSharedMemorySize, GEMM_SMEM);
    cudaFuncSetAttribute(attn_mma,
                         cudaFuncAttributeMaxDynamicSharedMemorySize, ATT_SMEM);

    dim3 blk(256);

    prep<<<16386, blk>>>(q, k, v, Wq, Wk, Wv, Wo, mk, pAh, pWh);
    gemm_qkv<<<dim3(8, 32, 3), blk, GEMM_SMEM>>>(
        pAh, pWh, bq, bk, bv, pQh, pKh, pVh);
    attn_mma<<<dim3(16, 16, 2), blk, ATT_SMEM>>>();   // writes fp16 ctx -> g_Ah
    gemm_out<<<dim3(8, 32), blk, GEMM_SMEM>>>(pAh, pWh, bo, out);
}

// round 14
// speedup vs baseline: 2.5065x; 1.0173x over previous
#include <cuda_runtime.h>
#include <cuda_fp16.h>
#include <math.h>
#include <stdint.h>

#define B_ 2
#define T_ 2048
#define D_ 1024
#define H_ 16
#define DH_ 64
#define SCALE_ 0.03125f     /* 1/sqrt(1024) exactly */

#define ASTRIDE ((size_t)4096*1024)
#define WSTRIDE ((size_t)1024*1024)

// ============================================================================
// Scratch (static device globals — no allocation in kernel_launch)
// g_Ah slab 0 doubles as the fp16 context buffer (attention epilogue output).
// ============================================================================
__device__ __half g_Ah[3*ASTRIDE];
__device__ __half g_Wh[4*WSTRIDE];
__device__ __half g_Qh[(size_t)B_*H_*T_*DH_];
__device__ __half g_Kh[(size_t)B_*H_*T_*DH_];   // compacted
__device__ __half g_Vh[(size_t)B_*H_*T_*DH_];   // compacted
__device__ int g_pos[B_*T_];
__device__ int g_cnt[B_];

// ============================================================================
// mma.sync / ldmatrix / cp.async helpers (base-target PTX)
// ============================================================================
__device__ __forceinline__ unsigned smem_u32(const void* p) {
    unsigned a;
    asm("{ .reg .u64 t; cvta.to.shared.u64 t, %1; cvt.u32.u64 %0, t; }"
        : "=r"(a) : "l"(p));
    return a;
}
__device__ __forceinline__ void mma_fp(float* c, const unsigned* a, const unsigned* b) {
    asm volatile(
        "mma.sync.aligned.m16n8k16.row.col.f32.f16.f16.f32 "
        "{%0,%1,%2,%3}, {%4,%5,%6,%7}, {%8,%9}, {%0,%1,%2,%3};"
        : "+f"(c[0]), "+f"(c[1]), "+f"(c[2]), "+f"(c[3])
        : "r"(a[0]), "r"(a[1]), "r"(a[2]), "r"(a[3]), "r"(b[0]), "r"(b[1]));
}
__device__ __forceinline__ void ldsm4(unsigned* r, unsigned a) {
    asm volatile("ldmatrix.sync.aligned.m8n8.x4.shared.b16 {%0,%1,%2,%3}, [%4];"
        : "=r"(r[0]), "=r"(r[1]), "=r"(r[2]), "=r"(r[3]) : "r"(a));
}
__device__ __forceinline__ void ldsm4t(unsigned* r, unsigned a) {
    asm volatile("ldmatrix.sync.aligned.m8n8.x4.trans.shared.b16 {%0,%1,%2,%3}, [%4];"
        : "=r"(r[0]), "=r"(r[1]), "=r"(r[2]), "=r"(r[3]) : "r"(a));
}
#define CP16(dst_u32, src_ptr) \
    asm volatile("cp.async.cg.shared.global [%0], [%1], 16;" \
        :: "r"(dst_u32), "l"(src_ptr) : "memory")
#define CP_COMMIT() asm volatile("cp.async.commit_group;" ::: "memory")
#define CP_WAIT1()  asm volatile("cp.async.wait_group 1;"  ::: "memory")

// ============================================================================
// prep: fused convA (q,k,v -> fp16), convW (4 weights -> fp16), mask scan.
// ============================================================================
__global__ void __launch_bounds__(256) prep(
    const float* __restrict__ q, const float* __restrict__ k,
    const float* __restrict__ v,
    const float* __restrict__ wq, const float* __restrict__ wk,
    const float* __restrict__ wv, const float* __restrict__ wo,
    const int* __restrict__ mask,
    __half* __restrict__ AhB, __half* __restrict__ WhB)
{
    const int bid = blockIdx.x, tid = threadIdx.x;
    if (bid < 12288) {
        const int z = bid >> 12;
        const float* src = (z == 0) ? q : (z == 1) ? k : v;
        int i = (bid & 4095) * 256 + tid;
        float4 w = ((const float4*)src)[i];
        __half2 a; a.x = __float2half_rn(w.x); a.y = __float2half_rn(w.y);
        __half2 b; b.x = __float2half_rn(w.z); b.y = __float2half_rn(w.w);
        __half* hi = AhB + (size_t)z*ASTRIDE;
        ((__half2*)hi)[2*i]   = a;
        ((__half2*)hi)[2*i+1] = b;
    } else if (bid < 16384) {
        const int zb = bid - 12288;
        const int z = zb >> 10;
        const float* src = (z == 0) ? wq : (z == 1) ? wk : (z == 2) ? wv : wo;
        int i = (zb & 1023) * 256 + tid;
        float4 w = ((const float4*)src)[i];
        __half2 a; a.x = __float2half_rn(w.x); a.y = __float2half_rn(w.y);
        __half2 b; b.x = __float2half_rn(w.z); b.y = __float2half_rn(w.w);
        __half* hi = WhB + (size_t)z*WSTRIDE;
        ((__half2*)hi)[2*i]   = a;
        ((__half2*)hi)[2*i+1] = b;
    } else {
        __shared__ int ps[256];
        const int b = bid - 16384;
        const int base = b*T_ + tid*8;
        int a[8], s = 0;
        #pragma unroll
        for (int j = 0; j < 8; j++) { a[j] = (mask[base + j] != 0); s += a[j]; }
        ps[tid] = s;
        __syncthreads();
        for (int off = 1; off < 256; off <<= 1) {
            int vsum = ps[tid] + ((tid >= off) ? ps[tid - off] : 0);
            __syncthreads();
            ps[tid] = vsum;
            __syncthreads();
        }
        int run = (tid > 0) ? ps[tid-1] : 0;
        #pragma unroll
        for (int j = 0; j < 8; j++) {
            g_pos[base + j] = a[j] ? run : -1;
            run += a[j];
        }
        if (tid == 255) g_cnt[b] = ps[255];
    }
}

// ============================================================================
// GEMM core: Y = Ah @ Wh + bias   (fp16 single-stream)
// cp.async 3-stage pipeline with K-chunk = 64 (16 iterations, 4 kk steps each).
// Stage: Ah[128][72]=18432B + Wh[64][136]=17408B = 35840B; 3 stages = 107.5KB.
// emode 0: Q proj -> fp16 scatter [B,H,T,64]
// emode 1: K/V proj -> fp16 scatter to COMPACTED rows
// emode 2: dense fp32 out
// ============================================================================
#define GST 35840
#define G_WH_OFF 18432
#define GEMM_SMEM (3*GST)

__device__ __forceinline__ void gemm_core(
    char* gsm,
    const __half* __restrict__ Ah, const __half* __restrict__ Wh,
    const float* __restrict__ bias,
    float* __restrict__ Yf, __half* __restrict__ Yh,
    int emode, int m0, int n0)
{
    const int tid = threadIdx.x, lane = tid & 31, wid = tid >> 5;
    const int wm = wid >> 2, wn = wid & 3;

    float c[4][4][4];
    #pragma unroll
    for (int i = 0; i < 4; i++)
        #pragma unroll
        for (int j = 0; j < 4; j++)
            #pragma unroll
            for (int e = 0; e < 4; e++) c[i][j][e] = 0.f;

    const int l15 = lane & 15, lh8 = (lane >> 4) << 3;
    const unsigned smb = smem_u32(gsm);

    // Chunk maps for K-chunk 64: A = 128x64 (8 chunks/row), W = 64x128 (16/row)
    int a_row[4], a_c8[4], w_row[4], w_c8[4];
    #pragma unroll
    for (int t = 0; t < 4; t++) {
        int ch = tid + t*256;
        a_row[t] = ch >> 3;  a_c8[t] = (ch & 7) << 3;
        w_row[t] = ch >> 4;  w_c8[t] = (ch & 15) << 3;
    }

    auto issue = [&](int s, int k0) {
        const unsigned base = smb + s*GST;
        #pragma unroll
        for (int t = 0; t < 4; t++) {
            unsigned aso = base + (unsigned)(a_row[t]*144 + a_c8[t]*2);
            size_t ago = (size_t)(m0 + a_row[t])*1024 + k0 + a_c8[t];
            CP16(aso, Ah + ago);
            unsigned wso = base + G_WH_OFF + (unsigned)(w_row[t]*272 + w_c8[t]*2);
            size_t wgo = (size_t)(k0 + w_row[t])*1024 + n0 + w_c8[t];
            CP16(wso, Wh + wgo);
        }
    };

    issue(0, 0);
    CP_COMMIT();
    issue(1, 64);
    CP_COMMIT();

    for (int kc = 0; kc < 16; kc++) {
        CP_WAIT1();
        __syncthreads();
        if (kc + 2 < 16) issue((kc + 2) % 3, (kc + 2) << 6);
        CP_COMMIT();

        const int buf = kc % 3;
        const __half* sAh = (const __half*)(gsm + buf*GST);
        const __half* sWh = (const __half*)(gsm + buf*GST + G_WH_OFF);

        #pragma unroll
        for (int kk = 0; kk < 64; kk += 16) {
            unsigned a[4][4], bh_[4][2], t4[4];
            #pragma unroll
            for (int mi = 0; mi < 4; mi++)
                ldsm4(a[mi], smem_u32(&sAh[(wm*64 + mi*16 + l15)*72 + kk + lh8]));
            #pragma unroll
            for (int p = 0; p < 2; p++) {
                ldsm4t(t4, smem_u32(&sWh[(kk + l15)*136 + wn*32 + p*16 + lh8]));
                bh_[2*p][0]=t4[0]; bh_[2*p][1]=t4[1];
                bh_[2*p+1][0]=t4[2]; bh_[2*p+1][1]=t4[3];
            }
            #pragma unroll
            for (int mi = 0; mi < 4; mi++)
                #pragma unroll
                for (int ni = 0; ni < 4; ni++) mma_fp(c[mi][ni], a[mi], bh_[ni]);
        }
    }

    // Epilogue
    const int rA = lane >> 2, c2 = (lane & 3) << 1;
    #pragma unroll
    for (int mi = 0; mi < 4; mi++) {
        const int rowA = m0 + wm*64 + mi*16 + rA;
        const int rowB = rowA + 8;
        int pA = rowA & (T_-1), pB = rowB & (T_-1);
        if (emode == 1) { pA = g_pos[rowA]; pB = g_pos[rowB]; }
        #pragma unroll
        for (int ni = 0; ni < 4; ni++) {
            const int col = n0 + wn*32 + ni*8 + c2;
            float2 bb = *(const float2*)(bias + col);
            float v00 = c[mi][ni][0] + bb.x, v01 = c[mi][ni][1] + bb.y;
            float v10 = c[mi][ni][2] + bb.x, v11 = c[mi][ni][3] + bb.y;
            if (emode == 2) {
                float2 w0; w0.x = v00; w0.y = v01;
                float2 w1; w1.x = v10; w1.y = v11;
                *(float2*)(Yf + (size_t)rowA * 1024 + col) = w0;
                *(float2*)(Yf + (size_t)rowB * 1024 + col) = w1;
            } else {
                const int hh = col >> 6, dd = col & 63;
                const int bA = rowA >> 11, bB = rowB >> 11;
                __half2 ph0; ph0.x = __float2half_rn(v00); ph0.y = __float2half_rn(v01);
                __half2 ph1; ph1.x = __float2half_rn(v10); ph1.y = __float2half_rn(v11);
                if (pA >= 0) {
                    size_t oA = (((size_t)(bA*H_ + hh))*T_ + pA)*64 + dd;
                    *(__half2*)(Yh + oA) = ph0;
                }
                if (pB >= 0) {
                    size_t oB = (((size_t)(bB*H_ + hh))*T_ + pB)*64 + dd;
                    *(__half2*)(Yh + oB) = ph1;
                }
            }
        }
    }
}

__global__ void __launch_bounds__(256, 2) gemm_qkv(
    const __half* __restrict__ AhB, const __half* __restrict__ WhB,
    const float* __restrict__ bq, const float* __restrict__ bk,
    const float* __restrict__ bv,
    __half* __restrict__ Qh, __half* __restrict__ Kh, __half* __restrict__ Vh)
{
    extern __shared__ __align__(16) char gsm[];
    const int z = blockIdx.z;
    const float* bias = (z == 0) ? bq : (z == 1) ? bk : bv;
    __half* Yh = (z == 0) ? Qh : (z == 1) ? Kh : Vh;
    gemm_core(gsm, AhB + z*ASTRIDE, WhB + z*WSTRIDE, bias,
              nullptr, Yh, (z == 0) ? 0 : 1,
              blockIdx.y << 7, blockIdx.x << 7);
}

__global__ void __launch_bounds__(256, 2) gemm_out(
    const __half* __restrict__ AhB, const __half* __restrict__ WhB,
    const float* __restrict__ bo, float* __restrict__ out)
{
    extern __shared__ __align__(16) char gsm[];
    gemm_core(gsm, AhB, WhB + 3*WSTRIDE, bo,
              out, nullptr, 2, blockIdx.y << 7, blockIdx.x << 7);
}

// ============================================================================
// Flash attention, warp-per-row-group layout (unchanged from R12 passing).
// ============================================================================
#define ATT_QH   0          /* 128 x 72 half = 18432 */
#define ATT_K    18432      /* 2 bufs x 9216 */
#define ATT_V    36864      /* 2 bufs x 9216 */
#define ATT_PH   55296      /* 128 x 72 half = 18432 */
#define ATT_SMEM 73728

__global__ void __launch_bounds__(256, 2) attn_mma()
{
    extern __shared__ __align__(16) char sm[];
    __half* sQh = (__half*)(sm + ATT_QH);
    __half* sPh = (__half*)(sm + ATT_PH);

    const int tid = threadIdx.x, lane = tid & 31, wid = tid >> 5;
    const int qt0 = blockIdx.x << 7;
    const int hh = blockIdx.y, bb = blockIdx.z;
    const size_t base = ((size_t)(bb*H_ + hh)) * T_ * DH_;
    const int nv = g_cnt[bb];
    const int nt = (nv + 63) >> 6;

    const int r = tid >> 1, cofs = (tid & 1) << 5;
    const int l15 = lane & 15, lh8 = (lane >> 4) << 3;
    const int bn  = (lane & 7) + ((lane >> 4) << 3), bk8 = ((lane >> 3) & 1) << 3;
    const int rA0 = lane >> 2, c2 = (lane & 3) << 1;

    const unsigned smK = smem_u32(sm + ATT_K);
    const unsigned smV = smem_u32(sm + ATT_V);

    int ld_row[2], ld_c8[2];
    #pragma unroll
    for (int t = 0; t < 2; t++) {
        int ch = tid + t*256;
        ld_row[t] = ch >> 3;
        ld_c8[t]  = (ch & 7) << 3;
    }

    // Load Q (persistent)
    {
        const uint4* s1 = (const uint4*)(g_Qh + base + (size_t)(qt0 + r)*64 + cofs);
        uint4* d1 = (uint4*)(sQh + r*72 + cofs);
        d1[0]=s1[0]; d1[1]=s1[1]; d1[2]=s1[2]; d1[3]=s1[3];
    }

    float lrunA = 0.f, lrunB = 0.f;
    float o[8][4];
    #pragma unroll
    for (int g = 0; g < 8; g++)
        #pragma unroll
        for (int e = 0; e < 4; e++) o[g][e] = 0.f;

    // Prologue: tile 0 -> buf 0
    #pragma unroll
    for (int t = 0; t < 2; t++) {
        unsigned so = (unsigned)((ld_row[t]*72 + ld_c8[t]) * 2);
        size_t go = base + (size_t)ld_row[t]*64 + ld_c8[t];
        CP16(smK + so, g_Kh + go);
        CP16(smV + so, g_Vh + go);
    }
    CP_COMMIT();

    const int prow = wid*16;   // this warp's q-row block

    for (int kt = 0; kt < nt; kt++) {
        const int buf = kt & 1;
        if (kt + 1 < nt) {
            const size_t gofs = base + ((size_t)(kt+1) << 6) * 64;
            const unsigned kb = smK + (buf ^ 1) * 9216u;
            const unsigned vb = smV + (buf ^ 1) * 9216u;
            #pragma unroll
            for (int t = 0; t < 2; t++) {
                unsigned so = (unsigned)((ld_row[t]*72 + ld_c8[t]) * 2);
                size_t go = gofs + (size_t)ld_row[t]*64 + ld_c8[t];
                CP16(kb + so, g_Kh + go);
                CP16(vb + so, g_Vh + go);
            }
        }
        CP_COMMIT();
        CP_WAIT1();
        __syncthreads();   // (A) current K/V buffer ready

        __half* sKh = (__half*)(sm + ATT_K + buf*9216);
        __half* sVh = (__half*)(sm + ATT_V + buf*9216);

        // ---- S = Qh·Kh : warp computes 16 rows x 64 keys ----
        float s[8][4];
        #pragma unroll
        for (int g = 0; g < 8; g++)
            #pragma unroll
            for (int e = 0; e < 4; e++) s[g][e] = 0.f;

        #pragma unroll
        for (int kk = 0; kk < 64; kk += 16) {
            unsigned a[4], bf[8][2], t4[4];
            ldsm4(a, smem_u32(&sQh[(prow + l15)*72 + kk + lh8]));
            #pragma unroll
            for (int g = 0; g < 4; g++) {
                ldsm4(t4, smem_u32(&sKh[(g*16 + bn)*72 + kk + bk8]));
                bf[2*g][0]=t4[0]; bf[2*g][1]=t4[1];
                bf[2*g+1][0]=t4[2]; bf[2*g+1][1]=t4[3];
            }
            #pragma unroll
            for (int G = 0; G < 8; G++) mma_fp(s[G], a, bf[G]);
        }

        // ---- warp-local softmax ----
        const int k0g = kt << 6;
        float sumA = 0.f, sumB = 0.f;
        #pragma unroll
        for (int G = 0; G < 8; G++) {
            const int col = G*8 + c2;
            const bool v0 = (k0g + col)     < nv;
            const bool v1 = (k0g + col + 1) < nv;
            float p00 = v0 ? __expf(s[G][0]*SCALE_) : 0.f;
            float p01 = v1 ? __expf(s[G][1]*SCALE_) : 0.f;
            float p10 = v0 ? __expf(s[G][2]*SCALE_) : 0.f;
            float p11 = v1 ? __expf(s[G][3]*SCALE_) : 0.f;
            sumA += p00 + p01;  sumB += p10 + p11;
            __half2 vh0; vh0.x = __float2half_rn(p00); vh0.y = __float2half_rn(p01);
            __half2 vh1; vh1.x = __float2half_rn(p10); vh1.y = __float2half_rn(p11);
            *(__half2*)(sPh + (prow + rA0)*72 + col)     = vh0;
            *(__half2*)(sPh + (prow + rA0 + 8)*72 + col) = vh1;
        }
        sumA += __shfl_xor_sync(0xffffffffu, sumA, 1);
        sumA += __shfl_xor_sync(0xffffffffu, sumA, 2);
        sumB += __shfl_xor_sync(0xffffffffu, sumB, 1);
        sumB += __shfl_xor_sync(0xffffffffu, sumB, 2);
        lrunA += sumA;
        lrunB += sumB;
        __syncwarp();

        // ---- O += Ph·Vh ----
        #pragma unroll
        for (int kk = 0; kk < 64; kk += 16) {
            unsigned pa[4], vf[8][2], t4[4];
            ldsm4(pa, smem_u32(&sPh[(prow + l15)*72 + kk + lh8]));
            #pragma unroll
            for (int g = 0; g < 4; g++) {
                ldsm4t(t4, smem_u32(&sVh[(kk + l15)*72 + g*16 + lh8]));
                vf[2*g][0]=t4[0]; vf[2*g][1]=t4[1];
                vf[2*g+1][0]=t4[2]; vf[2*g+1][1]=t4[3];
            }
            #pragma unroll
            for (int G = 0; G < 8; G++) mma_fp(o[G], pa, vf[G]);
        }
        __syncthreads();   // (C) all warps done with buf before refill
    }

    // ---- normalize + write fp16 ctx into g_Ah slab 0 ----
    const float invA = 1.f / lrunA, invB = 1.f / lrunB;
    const size_t rowA = (size_t)(bb*T_ + qt0 + prow + rA0) * D_ + hh*64;
    const size_t rowB = rowA + (size_t)8 * D_;
    #pragma unroll
    for (int G = 0; G < 8; G++) {
        const int col = G*8 + c2;
        __half2 w0; w0.x = __float2half_rn(o[G][0]*invA);
        w0.y = __float2half_rn(o[G][1]*invA);
        __half2 w1; w1.x = __float2half_rn(o[G][2]*invB);
        w1.y = __float2half_rn(o[G][3]*invB);
        *(__half2*)(g_Ah + rowA + col) = w0;
        *(__half2*)(g_Ah + rowB + col) = w1;
    }
}

// ============================================================================
extern "C" void kernel_launch(void* const* d_in, const int* in_sizes, int n_in,
                              void* d_out, int out_size)
{
    const float* q  = (const float*)d_in[0];
    const float* k  = (const float*)d_in[1];
    const float* v  = (const float*)d_in[2];
    const int*  mk  = (const int*)  d_in[3];
    const float* Wq = (const float*)d_in[4];
    const float* bq = (const float*)d_in[5];
    const float* Wk = (const float*)d_in[6];
    const float* bk = (const float*)d_in[7];
    const float* Wv = (const float*)d_in[8];
    const float* bv = (const float*)d_in[9];
    const float* Wo = (const float*)d_in[10];
    const float* bo = (const float*)d_in[11];
    float* out = (float*)d_out;

    __half *pAh, *pWh, *pQh, *pKh, *pVh;
    cudaGetSymbolAddress((void**)&pAh, g_Ah);
    cudaGetSymbolAddress((void**)&pWh, g_Wh);
    cudaGetSymbolAddress((void**)&pQh, g_Qh);
    cudaGetSymbolAddress((void**)&pKh, g_Kh);
    cudaGetSymbolAddress((void**)&pVh, g_Vh);

    cudaFuncSetAttribute(gemm_qkv,
                         cudaFuncAttributeMaxDynamicSharedMemorySize, GEMM_SMEM);
    cudaFuncSetAttribute(gemm_out,
                         cudaFuncAttributeMaxDynamicSharedMemorySize, GEMM_SMEM);
    cudaFuncSetAttribute(attn_mma,
                         cudaFuncAttributeMaxDynamicSharedMemorySize, ATT_SMEM);

    dim3 blk(256);

    prep<<<16386, blk>>>(q, k, v, Wq, Wk, Wv, Wo, mk, pAh, pWh);
    gemm_qkv<<<dim3(8, 32, 3), blk, GEMM_SMEM>>>(
        pAh, pWh, bq, bk, bv, pQh, pKh, pVh);
    attn_mma<<<dim3(16, 16, 2), blk, ATT_SMEM>>>();   // writes fp16 ctx -> g_Ah
    gemm_out<<<dim3(8, 32), blk, GEMM_SMEM>>>(pAh, pWh, bo, out);
}